// round 13
// baseline (speedup 1.0000x reference)
#include <cuda_runtime.h>
#include <cuda_bf16.h>

// CTC loss, two-phase:
//  Kernel A: parallel gather -> exp -> bf16-compact emission probs into a
//            64MB __device__ scratch ([t][b][lane] = uint4 holding 5 bf16
//            probs for states s = lane*5+j). Pure streaming, no serial chain.
//  Kernel B: bisected recurrence (fwd alpha t=1..tm, bwd gamma t=len-1..tm+1),
//            one 64-thread CTA per batch; each warp self-prefetches uint4
//            rows distance-2 with STATICALLY indexed register buffers.
//            Extended-range u*2^E arithmetic, block-rebased every 8 steps.

#define NST    5
#define RSTEPS 8
#define SENT   (-(1 << 28))

__device__ float    g_loss[1024];
__device__ unsigned g_cnt = 0;
__device__ uint4    g_p[1024u * 128u * 32u];   // 64 MB scratch

__device__ __forceinline__ float mkscale(int d) {   // 2^d, d in [-126,126]
    return __int_as_float((d + 127) << 23);
}

// ===================== Kernel A: gather + exp + compact =====================
__global__ void __launch_bounds__(256)
ctc_gather_kernel(const float* __restrict__ logp,
                  const int*   __restrict__ targets,
                  int T, int B, int C, int S)
{
    const int b     = blockIdx.x % B;
    const int chunk = blockIdx.x / B;
    const int w     = threadIdx.x >> 5;
    const int lane  = threadIdx.x & 31;
    const int L     = 2 * S + 1;
    const int* tgt  = targets + (size_t)b * S;

    int lab[NST];
#pragma unroll
    for (int j = 0; j < NST; ++j) {
        int s = lane * NST + j;
        lab[j] = (s < L && (s & 1)) ? tgt[s >> 1] : 0;
    }

    __shared__ __align__(16) float buf[8][256];
    const int t0 = chunk * 64 + w * 8;
    const size_t BC = (size_t)B * C;
    const float* src = logp + (size_t)b * C + lane * 8;

    float4 Ra[8], Rb[8];
#pragma unroll
    for (int i = 0; i < 8; ++i) {
        int tt = t0 + i; if (tt >= T) tt = T - 1;
        const float* r = src + (size_t)tt * BC;
        Ra[i] = *(const float4*)r;
        Rb[i] = *(const float4*)(r + 4);
    }
#pragma unroll
    for (int i = 0; i < 8; ++i) {
        ((float4*)&buf[w][lane * 8])[0] = Ra[i];
        ((float4*)&buf[w][lane * 8])[1] = Rb[i];
        __syncwarp();
        unsigned h[NST];
#pragma unroll
        for (int j = 0; j < NST; ++j) {
            float p = __expf(buf[w][lab[j]]);
            h[j] = (unsigned)__bfloat16_as_ushort(__float2bfloat16(p));
        }
        int tt = t0 + i;
        if (tt < T) {
            uint4 q;
            q.x = h[0] | (h[1] << 16);
            q.y = h[2] | (h[3] << 16);
            q.z = h[4];
            q.w = 0;
            g_p[((size_t)tt * B + b) * 32 + lane] = q;
        }
        __syncwarp();
    }
}

// ===================== Kernel B: bisected recurrence =====================

#define UNPACK_P(BUF)                                                        \
    do {                                                                     \
        _Pragma("unroll")                                                    \
        for (int k = 0; k < RSTEPS; ++k) {                                   \
            P[k][0] = __uint_as_float(BUF[k].x << 16);                       \
            P[k][1] = __uint_as_float(BUF[k].x & 0xffff0000u);               \
            P[k][2] = __uint_as_float(BUF[k].y << 16);                       \
            P[k][3] = __uint_as_float(BUF[k].y & 0xffff0000u);               \
            P[k][4] = __uint_as_float(BUF[k].z << 16);                       \
        }                                                                    \
    } while (0)

#define LOAD_F(m, BUF)                                                       \
    do {                                                                     \
        _Pragma("unroll")                                                    \
        for (int k = 0; k < RSTEPS; ++k) {                                   \
            int t = 1 + (m) * RSTEPS + k;                                    \
            if (t > lenm1) t = lenm1;                                        \
            BUF[k] = g_p[((size_t)t * B + b) * 32 + lane];                   \
        }                                                                    \
    } while (0)

#define LOAD_B(m, BUF)                                                       \
    do {                                                                     \
        _Pragma("unroll")                                                    \
        for (int k = 0; k < RSTEPS; ++k) {                                   \
            int t = lenm1 - 1 - (m) * RSTEPS - k;                            \
            if (t < 0) t = 0;                                                \
            BUF[k] = g_p[((size_t)t * B + b) * 32 + lane];                   \
        }                                                                    \
    } while (0)

#define FWD_BLOCK(nn)                                                        \
    do {                                                                     \
        int t0 = 1 + (nn) * RSTEPS;                                          \
        int Et[NST], mbt[NST];                                               \
        _Pragma("unroll")                                                    \
        for (int j = 0; j < NST; ++j) {                                      \
            int bits = __float_as_int(u[j]);                                 \
            int ex   = (bits >> 23) & 0xff;                                  \
            Et[j]  = (ex == 0) ? SENT : (Eb[j] + ex - 127);                  \
            mbt[j] = bits & 0x007fffff;                                      \
        }                                                                    \
        int P0 = Et[0];                                                      \
        int P1 = max(P0, Et[1]);                                             \
        int P2 = max(P1, Et[2]);                                             \
        int P3 = max(P2, Et[3]);                                             \
        int P4 = max(P3, Et[4]);                                             \
        int S4 = Et[4];                                                      \
        int S3 = max(Et[3], S4);                                             \
        int S2 = max(Et[2], S3);                                             \
        int S1 = max(Et[1], S2);                                             \
        int Mm1  = __shfl_up_sync(~0u, P4, 1);    if (lane < 1) Mm1  = SENT; \
        int Mm2  = __shfl_up_sync(~0u, P4, 2);    if (lane < 2) Mm2  = SENT; \
        int Mm3  = __shfl_up_sync(~0u, P4, 3);    if (lane < 3) Mm3  = SENT; \
        int S1m3 = __shfl_up_sync(~0u, S1, 3);    if (lane < 3) S1m3 = SENT; \
        int S2m3 = __shfl_up_sync(~0u, S2, 3);    if (lane < 3) S2m3 = SENT; \
        int S3m3 = __shfl_up_sync(~0u, S3, 3);    if (lane < 3) S3m3 = SENT; \
        int E4m4 = __shfl_up_sync(~0u, Et[4], 4); if (lane < 4) E4m4 = SENT; \
        int M12 = max(Mm1, Mm2);                                             \
        int E0 = max(max(P0, M12), max(Mm3, E4m4));                          \
        int E1 = max(max(P1, M12), Mm3);                                     \
        int E2 = max(max(P2, M12), S1m3);                                    \
        int E3 = max(max(P3, M12), S2m3);                                    \
        int E4 = max(max(P4, M12), S3m3);                                    \
        int En[NST] = {E0, E1, E2, E3, E4};                                  \
        _Pragma("unroll")                                                    \
        for (int j = 0; j < NST; ++j) {                                      \
            int d = Et[j] - En[j];                                           \
            u[j] = (d < -126 || Et[j] <= SENT) ? 0.0f                        \
                 : __int_as_float(mbt[j] | ((d + 127) << 23));               \
        }                                                                    \
        int E4m1 = __shfl_up_sync(~0u, E4, 1); if (lane < 1) E4m1 = SENT;    \
        int E3m1 = __shfl_up_sync(~0u, E3, 1); if (lane < 1) E3m1 = SENT;    \
        int Em1[NST] = {E4m1, E0, E1, E2, E3};                               \
        int Em2[NST] = {E3m1, E4m1, E0, E1, E2};                             \
        float sb[NST], sc[NST];                                              \
        _Pragma("unroll")                                                    \
        for (int j = 0; j < NST; ++j) {                                      \
            int db = min(Em1[j] - En[j], 126);                               \
            sb[j] = (db < -126 || Em1[j] <= SENT) ? 0.0f : mkscale(db);      \
            int dc = min(Em2[j] - En[j], 126);                               \
            float scv = (dc < -126 || Em2[j] <= SENT) ? 0.0f : mkscale(dc);  \
            sc[j] = skm[j] ? scv : 0.0f;                                     \
            Eb[j] = En[j];                                                   \
        }                                                                    \
        _Pragma("unroll")                                                    \
        for (int k = 0; k < RSTEPS; ++k) {                                   \
            int t = t0 + k;                                                  \
            if (t <= tm) {                                                   \
                float vm1 = __shfl_up_sync(~0u, u[4], 1);                    \
                float vm2 = __shfl_up_sync(~0u, u[3], 1);                    \
                if (lane == 0) { vm1 = 0.0f; vm2 = 0.0f; }                   \
                float n0 = fmaf(vm2,  sc[0], fmaf(vm1,  sb[0], u[0])) * P[k][0]; \
                float n1 = fmaf(vm1,  sc[1], fmaf(u[0], sb[1], u[1])) * P[k][1]; \
                float n2 = fmaf(u[0], sc[2], fmaf(u[1], sb[2], u[2])) * P[k][2]; \
                float n3 = fmaf(u[1], sc[3], fmaf(u[2], sb[3], u[3])) * P[k][3]; \
                float n4 = fmaf(u[2], sc[4], fmaf(u[3], sb[4], u[4])) * P[k][4]; \
                u[0] = n0; u[1] = n1; u[2] = n2; u[3] = n3; u[4] = n4;       \
            }                                                                \
        }                                                                    \
    } while (0)

#define BWD_BLOCK(mm)                                                        \
    do {                                                                     \
        int t0 = lenm1 - 1 - (mm) * RSTEPS;                                  \
        int Et[NST], mbt[NST];                                               \
        _Pragma("unroll")                                                    \
        for (int j = 0; j < NST; ++j) {                                      \
            int bits = __float_as_int(u[j]);                                 \
            int ex   = (bits >> 23) & 0xff;                                  \
            Et[j]  = (ex == 0) ? SENT : (Eb[j] + ex - 127);                  \
            mbt[j] = bits & 0x007fffff;                                      \
        }                                                                    \
        int Pm1 = max(Et[0], Et[1]);                                         \
        int Pm2 = max(Pm1, Et[2]);                                           \
        int Pm3 = max(Pm2, Et[3]);                                           \
        int M   = max(Pm3, Et[4]);                                           \
        int Sm4 = Et[4];                                                     \
        int Sm3 = max(Et[3], Sm4);                                           \
        int Sm2 = max(Et[2], Sm3);                                           \
        int Sm1 = max(Et[1], Sm2);                                           \
        int Sm0 = max(Et[0], Sm1);                                           \
        int Mp1  = __shfl_down_sync(~0u, M, 1);     if (lane > 30) Mp1  = SENT; \
        int Mp2  = __shfl_down_sync(~0u, M, 2);     if (lane > 29) Mp2  = SENT; \
        int Mp3  = __shfl_down_sync(~0u, M, 3);     if (lane > 28) Mp3  = SENT; \
        int P1p3 = __shfl_down_sync(~0u, Pm1, 3);   if (lane > 28) P1p3 = SENT; \
        int P2p3 = __shfl_down_sync(~0u, Pm2, 3);   if (lane > 28) P2p3 = SENT; \
        int P3p3 = __shfl_down_sync(~0u, Pm3, 3);   if (lane > 28) P3p3 = SENT; \
        int E0p4 = __shfl_down_sync(~0u, Et[0], 4); if (lane > 27) E0p4 = SENT; \
        int M12 = max(Mp1, Mp2);                                             \
        int E0 = max(max(Sm0, M12), P1p3);                                   \
        int E1 = max(max(Sm1, M12), P2p3);                                   \
        int E2 = max(max(Sm2, M12), P3p3);                                   \
        int E3 = max(max(Sm3, M12), Mp3);                                    \
        int E4 = max(max(Sm4, M12), max(Mp3, E0p4));                         \
        int En[NST] = {E0, E1, E2, E3, E4};                                  \
        _Pragma("unroll")                                                    \
        for (int j = 0; j < NST; ++j) {                                      \
            int d = Et[j] - En[j];                                           \
            u[j] = (d < -126 || Et[j] <= SENT) ? 0.0f                        \
                 : __int_as_float(mbt[j] | ((d + 127) << 23));               \
        }                                                                    \
        int E0p1 = __shfl_down_sync(~0u, E0, 1); if (lane > 30) E0p1 = SENT; \
        int E1p1 = __shfl_down_sync(~0u, E1, 1); if (lane > 30) E1p1 = SENT; \
        int Ep1[NST] = {E1, E2, E3, E4, E0p1};                               \
        int Ep2[NST] = {E2, E3, E4, E0p1, E1p1};                             \
        float sb[NST], sc[NST];                                              \
        _Pragma("unroll")                                                    \
        for (int j = 0; j < NST; ++j) {                                      \
            int db = min(Ep1[j] - En[j], 126);                               \
            sb[j] = (db < -126 || Ep1[j] <= SENT) ? 0.0f : mkscale(db);      \
            int dc = min(Ep2[j] - En[j], 126);                               \
            float scv = (dc < -126 || Ep2[j] <= SENT) ? 0.0f : mkscale(dc);  \
            sc[j] = sk2m[j] ? scv : 0.0f;                                    \
            Eb[j] = En[j];                                                   \
        }                                                                    \
        _Pragma("unroll")                                                    \
        for (int k = 0; k < RSTEPS; ++k) {                                   \
            int t = t0 - k;                                                  \
            if (t >= tmp1) {                                                 \
                float d0 = __shfl_down_sync(~0u, u[0], 1);                   \
                float d1 = __shfl_down_sync(~0u, u[1], 1);                   \
                if (lane == 31) { d0 = 0.0f; d1 = 0.0f; }                    \
                float n0 = fmaf(u[2], sc[0], fmaf(u[1], sb[0], u[0])) * P[k][0]; \
                float n1 = fmaf(u[3], sc[1], fmaf(u[2], sb[1], u[1])) * P[k][1]; \
                float n2 = fmaf(u[4], sc[2], fmaf(u[3], sb[2], u[2])) * P[k][2]; \
                float n3 = fmaf(d0,   sc[3], fmaf(u[4], sb[3], u[3])) * P[k][3]; \
                float n4 = fmaf(d1,   sc[4], fmaf(d0,   sb[4], u[4])) * P[k][4]; \
                u[0] = n0; u[1] = n1; u[2] = n2; u[3] = n3; u[4] = n4;       \
            }                                                                \
        }                                                                    \
    } while (0)

__global__ void __launch_bounds__(64, 1)
ctc_rec_kernel(const float* __restrict__ logp,
               const int*   __restrict__ targets,
               const int*   __restrict__ in_len,
               const int*   __restrict__ tgt_len,
               float*       __restrict__ out,
               int T, int B, int C, int S)
{
    const int b    = blockIdx.x;
    const int tid  = threadIdx.x;
    const int w    = tid >> 5;
    const int lane = tid & 31;
    const int L    = 2 * S + 1;
    const int* tgt = targets + (size_t)b * S;

    __shared__ float fvF[NST * 32]; __shared__ int feF[NST * 32];
    __shared__ float fvB[NST * 32]; __shared__ int feB[NST * 32];
    __shared__ float red[2];
    __shared__ int   s_last;
    if (tid == 0) s_last = 0;

    int len = in_len[b];
    if (len > T) len = T;
    if (len < 1) len = 1;
    const int lenm1 = len - 1;
    const int tm    = lenm1 >> 1;
    const int tmp1  = tm + 1;
    const bool use_gamma = (lenm1 > tm);

    if (w == 0) {
        // ---------------- forward (alpha) ----------------
        int skm[NST];
#pragma unroll
        for (int j = 0; j < NST; ++j) {
            int s = lane * NST + j;
            int sk = 0;
            if (s < L && s >= 3 && (s & 1)) {
                int lab = tgt[s >> 1];
                int lm2 = tgt[(s - 2) >> 1];
                if (lab != 0 && lab != lm2) sk = 1;
            }
            skm[j] = sk;
        }
        float u[NST]; int Eb[NST];
#pragma unroll
        for (int j = 0; j < NST; ++j) { u[j] = 0.0f; Eb[j] = SENT; }
        if (lane == 0) {
            const float* base = logp + (size_t)b * C;
            float y0 = __ldg(base) * 1.4426950408889634f;
            float f0 = floorf(y0); Eb[0] = (int)f0; u[0] = exp2f(y0 - f0);
            if (L > 1) {
                float y1 = __ldg(base + tgt[0]) * 1.4426950408889634f;
                float f1 = floorf(y1); Eb[1] = (int)f1; u[1] = exp2f(y1 - f1);
            }
        }

        uint4 bufA[RSTEPS], bufB[RSTEPS];
        float P[RSTEPS][NST];
        LOAD_F(0, bufA);
        LOAD_F(1, bufB);
        const int nb = (tm + RSTEPS - 1) / RSTEPS;
        for (int n = 0; n < nb; n += 2) {
            UNPACK_P(bufA);
            LOAD_F(n + 2, bufA);
            FWD_BLOCK(n);
            UNPACK_P(bufB);
            LOAD_F(n + 3, bufB);
            FWD_BLOCK(n + 1);
        }
#pragma unroll
        for (int j = 0; j < NST; ++j) {
            int bits = __float_as_int(u[j]);
            int ex   = (bits >> 23) & 0xff;
            feF[lane * NST + j] = (ex == 0) ? SENT : (Eb[j] + ex - 127);
            fvF[lane * NST + j] = (ex == 0) ? 0.0f
                                : __int_as_float((bits & 0x007fffff) | 0x3f800000);
        }
    } else {
        // ---------------- backward (gamma) ----------------
        int sk2m[NST];
#pragma unroll
        for (int j = 0; j < NST; ++j) {
            int s = lane * NST + j;
            int sk = 0;
            if ((s & 1) && (s + 2 <= L - 1)) {
                int lab  = tgt[s >> 1];
                int labp = tgt[(s >> 1) + 1];
                if (labp != 0 && labp != lab) sk = 1;
            }
            sk2m[j] = sk;
        }
        float u[NST]; int Eb[NST];
#pragma unroll
        for (int j = 0; j < NST; ++j) { u[j] = 0.0f; Eb[j] = SENT; }

        if (use_gamma) {
            int tl = tgt_len[b];
            int hi = 2 * tl; if (hi > L - 1) hi = L - 1;
            // init at t = len-1 from scratch row
            {
                uint4 q = g_p[((size_t)lenm1 * B + b) * 32 + lane];
                float p0 = __uint_as_float(q.x << 16);
                float p1 = __uint_as_float(q.x & 0xffff0000u);
                float p2 = __uint_as_float(q.y << 16);
                float p3 = __uint_as_float(q.y & 0xffff0000u);
                float p4 = __uint_as_float(q.z << 16);
                float pv[NST] = {p0, p1, p2, p3, p4};
#pragma unroll
                for (int j = 0; j < NST; ++j) {
                    int s = lane * NST + j;
                    if (tl > 0 && (s == hi || s == hi - 1)) {
                        u[j]  = pv[j];
                        Eb[j] = 0;
                    }
                }
            }
            uint4 bufA[RSTEPS], bufB[RSTEPS];
            float P[RSTEPS][NST];
            LOAD_B(0, bufA);
            LOAD_B(1, bufB);
            const int nbB = (lenm1 - 1 >= tmp1) ? ((lenm1 - 1 - tmp1) / RSTEPS + 1) : 0;
            for (int m = 0; m < nbB; m += 2) {
                UNPACK_P(bufA);
                LOAD_B(m + 2, bufA);
                BWD_BLOCK(m);
                UNPACK_P(bufB);
                LOAD_B(m + 3, bufB);
                BWD_BLOCK(m + 1);
            }
        }
#pragma unroll
        for (int j = 0; j < NST; ++j) {
            int bits = __float_as_int(u[j]);
            int ex   = (bits >> 23) & 0xff;
            feB[lane * NST + j] = (ex == 0) ? SENT : (Eb[j] + ex - 127);
            fvB[lane * NST + j] = (ex == 0) ? 0.0f
                                : __int_as_float((bits & 0x007fffff) | 0x3f800000);
        }
    }
    __syncthreads();

    // ---------------- combine: ll = sum_s alpha_tm[s] * beta_tm[s] --------
    if (w == 0) {
        int tl = tgt_len[b];
        int hi = 2 * tl; if (hi > L - 1) hi = L - 1;
        float Tv[NST]; int Te[NST];
#pragma unroll
        for (int j = 0; j < NST; ++j) { Tv[j] = 0.0f; Te[j] = SENT; }
        if (tl > 0) {
#pragma unroll
            for (int j = 0; j < NST; ++j) {
                int s = lane * NST + j;
                if (s < L) {
                    float va = fvF[s]; int ea = feF[s];
                    if (va != 0.0f) {
                        if (use_gamma) {
                            float g0v = fvB[s];     int g0e = feB[s];
                            float g1v = 0.0f;       int g1e = SENT;
                            float g2v = 0.0f;       int g2e = SENT;
                            if (s + 1 <= L - 1) { g1v = fvB[s + 1]; g1e = feB[s + 1]; }
                            int sk2 = 0;
                            if ((s & 1) && (s + 2 <= L - 1)) {
                                int lab  = tgt[s >> 1];
                                int labp = tgt[(s >> 1) + 1];
                                if (labp != 0 && labp != lab) sk2 = 1;
                            }
                            if (sk2) { g2v = fvB[s + 2]; g2e = feB[s + 2]; }
                            if (g0v == 0.0f) g0e = SENT;
                            if (g1v == 0.0f) g1e = SENT;
                            if (g2v == 0.0f) g2e = SENT;
                            int m = max(g0e, max(g1e, g2e));
                            if (m > SENT / 2) {
                                float bsum = 0.0f;
                                if (g0e > SENT / 2 && g0e - m >= -126) bsum += g0v * mkscale(g0e - m);
                                if (g1e > SENT / 2 && g1e - m >= -126) bsum += g1v * mkscale(g1e - m);
                                if (g2e > SENT / 2 && g2e - m >= -126) bsum += g2v * mkscale(g2e - m);
                                if (bsum > 0.0f) { Tv[j] = va * bsum; Te[j] = ea + m; }
                            }
                        } else {
                            if (s == hi || s == hi - 1) { Tv[j] = va; Te[j] = ea; }
                        }
                    }
                }
            }
        }
        int M = SENT;
#pragma unroll
        for (int j = 0; j < NST; ++j) if (Tv[j] > 0.0f) M = max(M, Te[j]);
#pragma unroll
        for (int o = 16; o > 0; o >>= 1)
            M = max(M, __shfl_xor_sync(~0u, M, o));
        double acc = 0.0;
#pragma unroll
        for (int j = 0; j < NST; ++j) {
            if (Tv[j] > 0.0f) {
                long long d = (long long)Te[j] - M;
                if (d > -1000) {
                    unsigned long long bits2 = (unsigned long long)(d + 1023) << 52;
                    acc += (double)Tv[j] * __longlong_as_double((long long)bits2);
                }
            }
        }
#pragma unroll
        for (int o = 16; o > 0; o >>= 1)
            acc += __shfl_xor_sync(~0u, acc, o);
        if (lane == 0) {
            float loss = 0.0f;
            if (tl > 0 && acc > 0.0 && M > SENT / 2) {
                double ll = ((double)M + log2(acc)) * 0.69314718055994530942;
                loss = (float)(-ll / (double)tl);
            }
            g_loss[b] = loss;
            __threadfence();
            unsigned old = atomicAdd(&g_cnt, 1);
            if (old == (unsigned)(gridDim.x - 1)) s_last = 1;
        }
    }
    __syncthreads();

    if (s_last) {
        __threadfence();
        float acc2 = 0.0f;
        for (int i2 = tid; i2 < B; i2 += 64) acc2 += g_loss[i2];
#pragma unroll
        for (int o = 16; o > 0; o >>= 1)
            acc2 += __shfl_xor_sync(~0u, acc2, o);
        if (lane == 0) red[w] = acc2;
        __syncthreads();
        if (tid == 0) {
            out[0] = (red[0] + red[1]) / (float)B;
            g_cnt = 0;   // reset for next graph replay
        }
    }
}

extern "C" void kernel_launch(void* const* d_in, const int* in_sizes, int n_in,
                              void* d_out, int out_size)
{
    const float* logp    = (const float*)d_in[0];
    const int*   targets = (const int*)d_in[1];
    const int*   in_len  = (const int*)d_in[2];
    const int*   tgt_len = (const int*)d_in[3];

    int B = in_sizes[2];                                   // 128
    int S = in_sizes[1] / B;                               // 64
    int C = 256;
    int T = (int)((size_t)in_sizes[0] / ((size_t)B * C));  // 1024

    int chunks = (T + 63) / 64;
    ctc_gather_kernel<<<B * chunks, 256>>>(logp, targets, T, B, C, S);
    ctc_rec_kernel<<<B, 64>>>(logp, targets, in_len, tgt_len,
                              (float*)d_out, T, B, C, S);
}

// round 14
// speedup vs baseline: 1.1175x; 1.1175x over previous
#include <cuda_runtime.h>
#include <cuda_bf16.h>

// CTC loss, two-phase, lean codegen:
//  Kernel A: parallel gather -> exp -> bf16-compact emission probs into a
//            padded [b][row][lane] scratch (row = t + TPAD, 512B per row).
//  Kernel B: bisected recurrence, one 64-thread CTA per batch (w0 fwd alpha,
//            w1 bwd gamma). Loads = 8x LDG.128 at immediate offsets per block
//            (one pointer add per block), triple-buffered distance-2.
//            bf16 probs unpacked inline per step. Extended-range u*2^E
//            arithmetic, rebase every 8 steps (exact identity, safe to over-run).

#define NST    5
#define RSTEPS 8
#define SENT   (-(1 << 28))
#define B_MAX  128
#define T_MAX  1024
#define TPAD   64
#define ROWS   (TPAD + T_MAX + TPAD)

__device__ float    g_loss[1024];
__device__ unsigned g_cnt = 0;
__device__ uint4    g_p2[(size_t)B_MAX * ROWS * 32];   // ~75 MB scratch

__device__ __forceinline__ float mkscale(int d) {   // 2^d, d in [-126,126]
    return __int_as_float((d + 127) << 23);
}

// ===================== Kernel A: gather + exp + compact =====================
__global__ void __launch_bounds__(256)
ctc_gather_kernel(const float* __restrict__ logp,
                  const int*   __restrict__ targets,
                  int T, int B, int C, int S)
{
    const int b     = blockIdx.x % B;
    const int chunk = blockIdx.x / B;
    const int w     = threadIdx.x >> 5;
    const int lane  = threadIdx.x & 31;
    const int L     = 2 * S + 1;
    const int* tgt  = targets + (size_t)b * S;

    int lab[NST];
#pragma unroll
    for (int j = 0; j < NST; ++j) {
        int s = lane * NST + j;
        lab[j] = (s < L && (s & 1)) ? tgt[s >> 1] : 0;
    }

    __shared__ __align__(16) float buf[8][256];
    const int t0 = chunk * 64 + w * 8;
    const size_t BC = (size_t)B * C;
    const float* src = logp + (size_t)b * C + lane * 8;

    float4 Ra[8], Rb[8];
#pragma unroll
    for (int i = 0; i < 8; ++i) {
        int tt = t0 + i; if (tt >= T) tt = T - 1;
        const float* r = src + (size_t)tt * BC;
        Ra[i] = *(const float4*)r;
        Rb[i] = *(const float4*)(r + 4);
    }
#pragma unroll
    for (int i = 0; i < 8; ++i) {
        ((float4*)&buf[w][lane * 8])[0] = Ra[i];
        ((float4*)&buf[w][lane * 8])[1] = Rb[i];
        __syncwarp();
        unsigned h[NST];
#pragma unroll
        for (int j = 0; j < NST; ++j) {
            float p = __expf(buf[w][lab[j]]);
            h[j] = (unsigned)__bfloat16_as_ushort(__float2bfloat16(p));
        }
        int tt = t0 + i;
        if (tt < T) {
            uint4 q;
            q.x = h[0] | (h[1] << 16);
            q.y = h[2] | (h[3] << 16);
            q.z = h[4];
            q.w = 0;
            g_p2[((size_t)b * ROWS + TPAD + tt) * 32 + lane] = q;
        }
        __syncwarp();
    }
}

// ===================== Kernel B: bisected recurrence =====================

#define LOADF(BUF)                                                           \
    do {                                                                     \
        _Pragma("unroll")                                                    \
        for (int k = 0; k < RSTEPS; ++k) BUF[k] = pF[k * 32];                \
        pF += RSTEPS * 32;                                                   \
    } while (0)

#define LOADB(BUF)                                                           \
    do {                                                                     \
        _Pragma("unroll")                                                    \
        for (int k = 0; k < RSTEPS; ++k) BUF[k] = pB[-(k * 32)];             \
        pB -= RSTEPS * 32;                                                   \
    } while (0)

#define FWD_BLOCK(nn, BUF)                                                   \
    do {                                                                     \
        int t0 = 1 + (nn) * RSTEPS;                                          \
        int Et[NST], mbt[NST];                                               \
        _Pragma("unroll")                                                    \
        for (int j = 0; j < NST; ++j) {                                      \
            int bits = __float_as_int(u[j]);                                 \
            int ex   = (bits >> 23) & 0xff;                                  \
            Et[j]  = (ex == 0) ? SENT : (Eb[j] + ex - 127);                  \
            mbt[j] = bits & 0x007fffff;                                      \
        }                                                                    \
        int P0 = Et[0];                                                      \
        int P1 = max(P0, Et[1]);                                             \
        int P2 = max(P1, Et[2]);                                             \
        int P3 = max(P2, Et[3]);                                             \
        int P4 = max(P3, Et[4]);                                             \
        int S4 = Et[4];                                                      \
        int S3 = max(Et[3], S4);                                             \
        int S2 = max(Et[2], S3);                                             \
        int S1 = max(Et[1], S2);                                             \
        int Mm1  = __shfl_up_sync(~0u, P4, 1);    if (lane < 1) Mm1  = SENT; \
        int Mm2  = __shfl_up_sync(~0u, P4, 2);    if (lane < 2) Mm2  = SENT; \
        int Mm3  = __shfl_up_sync(~0u, P4, 3);    if (lane < 3) Mm3  = SENT; \
        int S1m3 = __shfl_up_sync(~0u, S1, 3);    if (lane < 3) S1m3 = SENT; \
        int S2m3 = __shfl_up_sync(~0u, S2, 3);    if (lane < 3) S2m3 = SENT; \
        int S3m3 = __shfl_up_sync(~0u, S3, 3);    if (lane < 3) S3m3 = SENT; \
        int E4m4 = __shfl_up_sync(~0u, Et[4], 4); if (lane < 4) E4m4 = SENT; \
        int M12 = max(Mm1, Mm2);                                             \
        int E0 = max(max(P0, M12), max(Mm3, E4m4));                          \
        int E1 = max(max(P1, M12), Mm3);                                     \
        int E2 = max(max(P2, M12), S1m3);                                    \
        int E3 = max(max(P3, M12), S2m3);                                    \
        int E4 = max(max(P4, M12), S3m3);                                    \
        int En[NST] = {E0, E1, E2, E3, E4};                                  \
        _Pragma("unroll")                                                    \
        for (int j = 0; j < NST; ++j) {                                      \
            int d = Et[j] - En[j];                                           \
            u[j] = (d < -126 || Et[j] <= SENT) ? 0.0f                        \
                 : __int_as_float(mbt[j] | ((d + 127) << 23));               \
        }                                                                    \
        int E4m1 = __shfl_up_sync(~0u, E4, 1); if (lane < 1) E4m1 = SENT;    \
        int E3m1 = __shfl_up_sync(~0u, E3, 1); if (lane < 1) E3m1 = SENT;    \
        int Em1[NST] = {E4m1, E0, E1, E2, E3};                               \
        int Em2[NST] = {E3m1, E4m1, E0, E1, E2};                             \
        float sb[NST], sc[NST];                                              \
        _Pragma("unroll")                                                    \
        for (int j = 0; j < NST; ++j) {                                      \
            int db = min(Em1[j] - En[j], 126);                               \
            sb[j] = (db < -126 || Em1[j] <= SENT) ? 0.0f : mkscale(db);      \
            int dc = min(Em2[j] - En[j], 126);                               \
            float scv = (dc < -126 || Em2[j] <= SENT) ? 0.0f : mkscale(dc);  \
            sc[j] = skm[j] ? scv : 0.0f;                                     \
            Eb[j] = En[j];                                                   \
        }                                                                    \
        _Pragma("unroll")                                                    \
        for (int k = 0; k < RSTEPS; ++k) {                                   \
            int t = t0 + k;                                                  \
            if (t <= tm) {                                                   \
                float p0 = __uint_as_float(BUF[k].x << 16);                  \
                float p1 = __uint_as_float(BUF[k].x & 0xffff0000u);          \
                float p2 = __uint_as_float(BUF[k].y << 16);                  \
                float p3 = __uint_as_float(BUF[k].y & 0xffff0000u);          \
                float p4 = __uint_as_float(BUF[k].z << 16);                  \
                float vm1 = __shfl_up_sync(~0u, u[4], 1);                    \
                float vm2 = __shfl_up_sync(~0u, u[3], 1);                    \
                if (lane == 0) { vm1 = 0.0f; vm2 = 0.0f; }                   \
                float n0 = fmaf(vm2,  sc[0], fmaf(vm1,  sb[0], u[0])) * p0;  \
                float n1 = fmaf(vm1,  sc[1], fmaf(u[0], sb[1], u[1])) * p1;  \
                float n2 = fmaf(u[0], sc[2], fmaf(u[1], sb[2], u[2])) * p2;  \
                float n3 = fmaf(u[1], sc[3], fmaf(u[2], sb[3], u[3])) * p3;  \
                float n4 = fmaf(u[2], sc[4], fmaf(u[3], sb[4], u[4])) * p4;  \
                u[0] = n0; u[1] = n1; u[2] = n2; u[3] = n3; u[4] = n4;       \
            }                                                                \
        }                                                                    \
    } while (0)

#define BWD_BLOCK(mm, BUF)                                                   \
    do {                                                                     \
        int t0 = lenm1 - 1 - (mm) * RSTEPS;                                  \
        int Et[NST], mbt[NST];                                               \
        _Pragma("unroll")                                                    \
        for (int j = 0; j < NST; ++j) {                                      \
            int bits = __float_as_int(u[j]);                                 \
            int ex   = (bits >> 23) & 0xff;                                  \
            Et[j]  = (ex == 0) ? SENT : (Eb[j] + ex - 127);                  \
            mbt[j] = bits & 0x007fffff;                                      \
        }                                                                    \
        int Pm1 = max(Et[0], Et[1]);                                         \
        int Pm2 = max(Pm1, Et[2]);                                           \
        int Pm3 = max(Pm2, Et[3]);                                           \
        int M   = max(Pm3, Et[4]);                                           \
        int Sm4 = Et[4];                                                     \
        int Sm3 = max(Et[3], Sm4);                                           \
        int Sm2 = max(Et[2], Sm3);                                           \
        int Sm1 = max(Et[1], Sm2);                                           \
        int Sm0 = max(Et[0], Sm1);                                           \
        int Mp1  = __shfl_down_sync(~0u, M, 1);     if (lane > 30) Mp1  = SENT; \
        int Mp2  = __shfl_down_sync(~0u, M, 2);     if (lane > 29) Mp2  = SENT; \
        int Mp3  = __shfl_down_sync(~0u, M, 3);     if (lane > 28) Mp3  = SENT; \
        int P1p3 = __shfl_down_sync(~0u, Pm1, 3);   if (lane > 28) P1p3 = SENT; \
        int P2p3 = __shfl_down_sync(~0u, Pm2, 3);   if (lane > 28) P2p3 = SENT; \
        int P3p3 = __shfl_down_sync(~0u, Pm3, 3);   if (lane > 28) P3p3 = SENT; \
        int E0p4 = __shfl_down_sync(~0u, Et[0], 4); if (lane > 27) E0p4 = SENT; \
        int M12 = max(Mp1, Mp2);                                             \
        int E0 = max(max(Sm0, M12), P1p3);                                   \
        int E1 = max(max(Sm1, M12), P2p3);                                   \
        int E2 = max(max(Sm2, M12), P3p3);                                   \
        int E3 = max(max(Sm3, M12), Mp3);                                    \
        int E4 = max(max(Sm4, M12), max(Mp3, E0p4));                         \
        int En[NST] = {E0, E1, E2, E3, E4};                                  \
        _Pragma("unroll")                                                    \
        for (int j = 0; j < NST; ++j) {                                      \
            int d = Et[j] - En[j];                                           \
            u[j] = (d < -126 || Et[j] <= SENT) ? 0.0f                        \
                 : __int_as_float(mbt[j] | ((d + 127) << 23));               \
        }                                                                    \
        int E0p1 = __shfl_down_sync(~0u, E0, 1); if (lane > 30) E0p1 = SENT; \
        int E1p1 = __shfl_down_sync(~0u, E1, 1); if (lane > 30) E1p1 = SENT; \
        int Ep1[NST] = {E1, E2, E3, E4, E0p1};                               \
        int Ep2[NST] = {E2, E3, E4, E0p1, E1p1};                             \
        float sb[NST], sc[NST];                                              \
        _Pragma("unroll")                                                    \
        for (int j = 0; j < NST; ++j) {                                      \
            int db = min(Ep1[j] - En[j], 126);                               \
            sb[j] = (db < -126 || Ep1[j] <= SENT) ? 0.0f : mkscale(db);      \
            int dc = min(Ep2[j] - En[j], 126);                               \
            float scv = (dc < -126 || Ep2[j] <= SENT) ? 0.0f : mkscale(dc);  \
            sc[j] = sk2m[j] ? scv : 0.0f;                                    \
            Eb[j] = En[j];                                                   \
        }                                                                    \
        _Pragma("unroll")                                                    \
        for (int k = 0; k < RSTEPS; ++k) {                                   \
            int t = t0 - k;                                                  \
            if (t >= tmp1) {                                                 \
                float p0 = __uint_as_float(BUF[k].x << 16);                  \
                float p1 = __uint_as_float(BUF[k].x & 0xffff0000u);          \
                float p2 = __uint_as_float(BUF[k].y << 16);                  \
                float p3 = __uint_as_float(BUF[k].y & 0xffff0000u);          \
                float p4 = __uint_as_float(BUF[k].z << 16);                  \
                float d0 = __shfl_down_sync(~0u, u[0], 1);                   \
                float d1 = __shfl_down_sync(~0u, u[1], 1);                   \
                if (lane == 31) { d0 = 0.0f; d1 = 0.0f; }                    \
                float n0 = fmaf(u[2], sc[0], fmaf(u[1], sb[0], u[0])) * p0;  \
                float n1 = fmaf(u[3], sc[1], fmaf(u[2], sb[1], u[1])) * p1;  \
                float n2 = fmaf(u[4], sc[2], fmaf(u[3], sb[2], u[2])) * p2;  \
                float n3 = fmaf(d0,   sc[3], fmaf(u[4], sb[3], u[3])) * p3;  \
                float n4 = fmaf(d1,   sc[4], fmaf(d0,   sb[4], u[4])) * p4;  \
                u[0] = n0; u[1] = n1; u[2] = n2; u[3] = n3; u[4] = n4;       \
            }                                                                \
        }                                                                    \
    } while (0)

__global__ void __launch_bounds__(64, 1)
ctc_rec_kernel(const int* __restrict__ targets,
               const int* __restrict__ in_len,
               const int* __restrict__ tgt_len,
               float*     __restrict__ out,
               int T, int B, int C, int S)
{
    const int b    = blockIdx.x;
    const int tid  = threadIdx.x;
    const int w    = tid >> 5;
    const int lane = tid & 31;
    const int L    = 2 * S + 1;
    const int* tgt = targets + (size_t)b * S;

    __shared__ float fvF[NST * 32]; __shared__ int feF[NST * 32];
    __shared__ float fvB[NST * 32]; __shared__ int feB[NST * 32];
    __shared__ float red[2];
    __shared__ int   s_last;
    if (tid == 0) s_last = 0;

    int len = in_len[b];
    if (len > T) len = T;
    if (len < 1) len = 1;
    const int lenm1 = len - 1;
    const int tm    = lenm1 >> 1;
    const int tmp1  = tm + 1;
    const bool use_gamma = (lenm1 > tm);

    const uint4* rowbase = g_p2 + ((size_t)b * ROWS + TPAD) * 32 + lane;

    if (w == 0) {
        // ---------------- forward (alpha) ----------------
        int skm[NST];
#pragma unroll
        for (int j = 0; j < NST; ++j) {
            int s = lane * NST + j;
            int sk = 0;
            if (s < L && s >= 3 && (s & 1)) {
                int lab = tgt[s >> 1];
                int lm2 = tgt[(s - 2) >> 1];
                if (lab != 0 && lab != lm2) sk = 1;
            }
            skm[j] = sk;
        }
        float u[NST]; int Eb[NST];
#pragma unroll
        for (int j = 0; j < NST; ++j) { u[j] = 0.0f; Eb[j] = SENT; }
        {   // init t=0 from scratch row 0 (lane 0 owns states 0,1)
            uint4 q0 = rowbase[0];
            if (lane == 0) {
                float p0 = __uint_as_float(q0.x << 16);
                float p1 = __uint_as_float(q0.x & 0xffff0000u);
                if (p0 > 0.0f) { u[0] = p0; Eb[0] = 0; }
                if (L > 1 && p1 > 0.0f) { u[1] = p1; Eb[1] = 0; }
            }
        }

        const uint4* pF = rowbase + 32;      // row t=1
        uint4 b0[RSTEPS], b1[RSTEPS], b2[RSTEPS];
        LOADF(b0); LOADF(b1); LOADF(b2);
        const int nb = (tm + RSTEPS - 1) / RSTEPS;
        for (int n = 0; n < nb; n += 3) {
            FWD_BLOCK(n, b0);     LOADF(b0);
            FWD_BLOCK(n + 1, b1); LOADF(b1);
            FWD_BLOCK(n + 2, b2); LOADF(b2);
        }
#pragma unroll
        for (int j = 0; j < NST; ++j) {
            int bits = __float_as_int(u[j]);
            int ex   = (bits >> 23) & 0xff;
            feF[lane * NST + j] = (ex == 0) ? SENT : (Eb[j] + ex - 127);
            fvF[lane * NST + j] = (ex == 0) ? 0.0f
                                : __int_as_float((bits & 0x007fffff) | 0x3f800000);
        }
    } else {
        // ---------------- backward (gamma) ----------------
        int sk2m[NST];
#pragma unroll
        for (int j = 0; j < NST; ++j) {
            int s = lane * NST + j;
            int sk = 0;
            if ((s & 1) && (s + 2 <= L - 1)) {
                int lab  = tgt[s >> 1];
                int labp = tgt[(s >> 1) + 1];
                if (labp != 0 && labp != lab) sk = 1;
            }
            sk2m[j] = sk;
        }
        float u[NST]; int Eb[NST];
#pragma unroll
        for (int j = 0; j < NST; ++j) { u[j] = 0.0f; Eb[j] = SENT; }

        if (use_gamma) {
            int tl = tgt_len[b];
            int hi = 2 * tl; if (hi > L - 1) hi = L - 1;
            {   // init at t = len-1
                uint4 q = rowbase[(size_t)lenm1 * 32];
                float pv[NST];
                pv[0] = __uint_as_float(q.x << 16);
                pv[1] = __uint_as_float(q.x & 0xffff0000u);
                pv[2] = __uint_as_float(q.y << 16);
                pv[3] = __uint_as_float(q.y & 0xffff0000u);
                pv[4] = __uint_as_float(q.z << 16);
#pragma unroll
                for (int j = 0; j < NST; ++j) {
                    int s = lane * NST + j;
                    if (tl > 0 && (s == hi || s == hi - 1) && pv[j] > 0.0f) {
                        u[j]  = pv[j];
                        Eb[j] = 0;
                    }
                }
            }
            const uint4* pB = rowbase + (size_t)(lenm1 - 1) * 32;
            uint4 b0[RSTEPS], b1[RSTEPS], b2[RSTEPS];
            LOADB(b0); LOADB(b1); LOADB(b2);
            const int nbB = (lenm1 - 1 - tmp1) / RSTEPS + 1;
            for (int m = 0; m < nbB; m += 3) {
                BWD_BLOCK(m, b0);     LOADB(b0);
                BWD_BLOCK(m + 1, b1); LOADB(b1);
                BWD_BLOCK(m + 2, b2); LOADB(b2);
            }
        }
#pragma unroll
        for (int j = 0; j < NST; ++j) {
            int bits = __float_as_int(u[j]);
            int ex   = (bits >> 23) & 0xff;
            feB[lane * NST + j] = (ex == 0) ? SENT : (Eb[j] + ex - 127);
            fvB[lane * NST + j] = (ex == 0) ? 0.0f
                                : __int_as_float((bits & 0x007fffff) | 0x3f800000);
        }
    }
    __syncthreads();

    // ---------------- combine: ll = sum_s alpha_tm[s] * beta_tm[s] --------
    if (w == 0) {
        int tl = tgt_len[b];
        int hi = 2 * tl; if (hi > L - 1) hi = L - 1;
        float Tv[NST]; int Te[NST];
#pragma unroll
        for (int j = 0; j < NST; ++j) { Tv[j] = 0.0f; Te[j] = SENT; }
        if (tl > 0) {
#pragma unroll
            for (int j = 0; j < NST; ++j) {
                int s = lane * NST + j;
                if (s < L) {
                    float va = fvF[s]; int ea = feF[s];
                    if (va != 0.0f) {
                        if (use_gamma) {
                            float g0v = fvB[s];     int g0e = feB[s];
                            float g1v = 0.0f;       int g1e = SENT;
                            float g2v = 0.0f;       int g2e = SENT;
                            if (s + 1 <= L - 1) { g1v = fvB[s + 1]; g1e = feB[s + 1]; }
                            int sk2 = 0;
                            if ((s & 1) && (s + 2 <= L - 1)) {
                                int lab  = tgt[s >> 1];
                                int labp = tgt[(s >> 1) + 1];
                                if (labp != 0 && labp != lab) sk2 = 1;
                            }
                            if (sk2) { g2v = fvB[s + 2]; g2e = feB[s + 2]; }
                            if (g0v == 0.0f) g0e = SENT;
                            if (g1v == 0.0f) g1e = SENT;
                            if (g2v == 0.0f) g2e = SENT;
                            int m = max(g0e, max(g1e, g2e));
                            if (m > SENT / 2) {
                                float bsum = 0.0f;
                                if (g0e > SENT / 2 && g0e - m >= -126) bsum += g0v * mkscale(g0e - m);
                                if (g1e > SENT / 2 && g1e - m >= -126) bsum += g1v * mkscale(g1e - m);
                                if (g2e > SENT / 2 && g2e - m >= -126) bsum += g2v * mkscale(g2e - m);
                                if (bsum > 0.0f) { Tv[j] = va * bsum; Te[j] = ea + m; }
                            }
                        } else {
                            if (s == hi || s == hi - 1) { Tv[j] = va; Te[j] = ea; }
                        }
                    }
                }
            }
        }
        int M = SENT;
#pragma unroll
        for (int j = 0; j < NST; ++j) if (Tv[j] > 0.0f) M = max(M, Te[j]);
#pragma unroll
        for (int o = 16; o > 0; o >>= 1)
            M = max(M, __shfl_xor_sync(~0u, M, o));
        double acc = 0.0;
#pragma unroll
        for (int j = 0; j < NST; ++j) {
            if (Tv[j] > 0.0f) {
                long long d = (long long)Te[j] - M;
                if (d > -1000) {
                    unsigned long long bits2 = (unsigned long long)(d + 1023) << 52;
                    acc += (double)Tv[j] * __longlong_as_double((long long)bits2);
                }
            }
        }
#pragma unroll
        for (int o = 16; o > 0; o >>= 1)
            acc += __shfl_xor_sync(~0u, acc, o);
        if (lane == 0) {
            float loss = 0.0f;
            if (tl > 0 && acc > 0.0 && M > SENT / 2) {
                double ll = ((double)M + log2(acc)) * 0.69314718055994530942;
                loss = (float)(-ll / (double)tl);
            }
            g_loss[b] = loss;
            __threadfence();
            unsigned old = atomicAdd(&g_cnt, 1);
            if (old == (unsigned)(gridDim.x - 1)) s_last = 1;
        }
    }
    __syncthreads();

    if (s_last) {
        __threadfence();
        float acc2 = 0.0f;
        for (int i2 = tid; i2 < B; i2 += 64) acc2 += g_loss[i2];
#pragma unroll
        for (int o = 16; o > 0; o >>= 1)
            acc2 += __shfl_xor_sync(~0u, acc2, o);
        if (lane == 0) red[w] = acc2;
        __syncthreads();
        if (tid == 0) {
            out[0] = (red[0] + red[1]) / (float)B;
            g_cnt = 0;   // reset for next graph replay
        }
    }
}

extern "C" void kernel_launch(void* const* d_in, const int* in_sizes, int n_in,
                              void* d_out, int out_size)
{
    const float* logp    = (const float*)d_in[0];
    const int*   targets = (const int*)d_in[1];
    const int*   in_len  = (const int*)d_in[2];
    const int*   tgt_len = (const int*)d_in[3];

    int B = in_sizes[2];                                   // 128
    int S = in_sizes[1] / B;                               // 64
    int C = 256;
    int T = (int)((size_t)in_sizes[0] / ((size_t)B * C));  // 1024

    int chunks = (T + 63) / 64;
    ctc_gather_kernel<<<B * chunks, 256>>>(logp, targets, T, B, C, S);
    ctc_rec_kernel<<<B, 64>>>(targets, in_len, tgt_len,
                              (float*)d_out, T, B, C, S);
}

// round 15
// speedup vs baseline: 1.9510x; 1.7459x over previous
#include <cuda_runtime.h>

// CTC loss. Two CTAs per batch element: dir 0 = forward alpha over t=1..tm,
// dir 1 = backward gamma over t=len-1..tm+1. Each CTA: 1 compute warp +
// 7 loader warps. Extended-range u*2^E arithmetic, block-rebase every 8 steps.
// R15: compute loops split into UNGUARDED full blocks (straight-line, no
// per-step branches, no clamps) + one guarded tail block.

#define NST    5
#define RSTEPS 8
#define RD     32
#define LEAD   24
#define DEPTH  6
#define NLD    7
#define SENT   (-(1 << 28))

__device__ float    g_loss[1024];
__device__ unsigned g_cnt = 0;
__device__ int      g_pair[1024];
__device__ float    g_fv[2][1024][NST * 32];
__device__ int      g_fe[2][1024][NST * 32];

__device__ __forceinline__ void st_release_cta(int* p, int v) {
    asm volatile("st.release.cta.b32 [%0], %1;" :: "l"(p), "r"(v) : "memory");
}
__device__ __forceinline__ int ld_acquire_cta(const int* p) {
    int v;
    asm volatile("ld.acquire.cta.b32 %0, [%1];" : "=r"(v) : "l"(p) : "memory");
    return v;
}
__device__ __forceinline__ int iclamp(int x, int lo, int hi) {
    return min(max(x, lo), hi);
}
__device__ __forceinline__ float mkscale(int d) {
    return __int_as_float((d + 127) << 23);
}

// ---------------- forward block (8 steps) ----------------
template<bool FULL>
__device__ __forceinline__ void fwd_block(
    int t0, int tm, int lane,
    float (*ring)[NST * 32],
    const int (&skm)[NST], float (&u)[NST], int (&Eb)[NST])
{
    float P[RSTEPS][NST];
#pragma unroll
    for (int k = 0; k < RSTEPS; ++k) {
        int t = t0 + k;
        if (!FULL) { if (t > tm) t = tm; }
        const float* rp = &ring[t & (RD - 1)][0];
#pragma unroll
        for (int j = 0; j < NST; ++j) P[k][j] = rp[j * 32 + lane];
    }
    // rebase: E'[s] = max(Et[s-16..s])
    int Et[NST], mbt[NST];
#pragma unroll
    for (int j = 0; j < NST; ++j) {
        int bits = __float_as_int(u[j]);
        int ex   = (bits >> 23) & 0xff;
        Et[j]  = (ex == 0) ? SENT : (Eb[j] + ex - 127);
        mbt[j] = bits & 0x007fffff;
    }
    int P0 = Et[0];
    int P1 = max(P0, Et[1]);
    int P2 = max(P1, Et[2]);
    int P3 = max(P2, Et[3]);
    int P4 = max(P3, Et[4]);
    int S4 = Et[4];
    int S3 = max(Et[3], S4);
    int S2 = max(Et[2], S3);
    int S1 = max(Et[1], S2);
    int Mm1  = __shfl_up_sync(~0u, P4, 1);    if (lane < 1) Mm1  = SENT;
    int Mm2  = __shfl_up_sync(~0u, P4, 2);    if (lane < 2) Mm2  = SENT;
    int Mm3  = __shfl_up_sync(~0u, P4, 3);    if (lane < 3) Mm3  = SENT;
    int S1m3 = __shfl_up_sync(~0u, S1, 3);    if (lane < 3) S1m3 = SENT;
    int S2m3 = __shfl_up_sync(~0u, S2, 3);    if (lane < 3) S2m3 = SENT;
    int S3m3 = __shfl_up_sync(~0u, S3, 3);    if (lane < 3) S3m3 = SENT;
    int E4m4 = __shfl_up_sync(~0u, Et[4], 4); if (lane < 4) E4m4 = SENT;
    int M12 = max(Mm1, Mm2);
    int E0 = max(max(P0, M12), max(Mm3, E4m4));
    int E1 = max(max(P1, M12), Mm3);
    int E2 = max(max(P2, M12), S1m3);
    int E3 = max(max(P3, M12), S2m3);
    int E4 = max(max(P4, M12), S3m3);
    int En[NST] = {E0, E1, E2, E3, E4};
#pragma unroll
    for (int j = 0; j < NST; ++j) {
        int d = Et[j] - En[j];
        u[j] = (d < -126 || Et[j] <= SENT) ? 0.0f
             : __int_as_float(mbt[j] | ((d + 127) << 23));
    }
    int E4m1 = __shfl_up_sync(~0u, E4, 1); if (lane < 1) E4m1 = SENT;
    int E3m1 = __shfl_up_sync(~0u, E3, 1); if (lane < 1) E3m1 = SENT;
    int Em1[NST] = {E4m1, E0, E1, E2, E3};
    int Em2[NST] = {E3m1, E4m1, E0, E1, E2};
    float sb[NST], sc[NST];
#pragma unroll
    for (int j = 0; j < NST; ++j) {
        int db = min(Em1[j] - En[j], 126);
        sb[j] = (db < -126 || Em1[j] <= SENT) ? 0.0f : mkscale(db);
        int dc = min(Em2[j] - En[j], 126);
        float scv = (dc < -126 || Em2[j] <= SENT) ? 0.0f : mkscale(dc);
        sc[j] = skm[j] ? scv : 0.0f;
        Eb[j] = En[j];
    }
#pragma unroll
    for (int k = 0; k < RSTEPS; ++k) {
        if (FULL || (t0 + k <= tm)) {
            float vm1 = __shfl_up_sync(~0u, u[4], 1);
            float vm2 = __shfl_up_sync(~0u, u[3], 1);
            if (lane == 0) { vm1 = 0.0f; vm2 = 0.0f; }
            float n0 = fmaf(vm2,  sc[0], fmaf(vm1,  sb[0], u[0])) * P[k][0];
            float n1 = fmaf(vm1,  sc[1], fmaf(u[0], sb[1], u[1])) * P[k][1];
            float n2 = fmaf(u[0], sc[2], fmaf(u[1], sb[2], u[2])) * P[k][2];
            float n3 = fmaf(u[1], sc[3], fmaf(u[2], sb[3], u[3])) * P[k][3];
            float n4 = fmaf(u[2], sc[4], fmaf(u[3], sb[4], u[4])) * P[k][4];
            u[0] = n0; u[1] = n1; u[2] = n2; u[3] = n3; u[4] = n4;
        }
    }
}

// ---------------- backward block (8 steps, descending t) ----------------
template<bool FULL>
__device__ __forceinline__ void bwd_block(
    int t0, int tmp1, int lane,
    float (*ring)[NST * 32],
    const int (&sk2m)[NST], float (&u)[NST], int (&Eb)[NST])
{
    float P[RSTEPS][NST];
#pragma unroll
    for (int k = 0; k < RSTEPS; ++k) {
        int t = t0 - k;
        if (!FULL) { if (t < tmp1) t = tmp1; }
        const float* rp = &ring[t & (RD - 1)][0];
#pragma unroll
        for (int j = 0; j < NST; ++j) P[k][j] = rp[j * 32 + lane];
    }
    // rebase: E'[s] = max(Et[s..s+16])
    int Et[NST], mbt[NST];
#pragma unroll
    for (int j = 0; j < NST; ++j) {
        int bits = __float_as_int(u[j]);
        int ex   = (bits >> 23) & 0xff;
        Et[j]  = (ex == 0) ? SENT : (Eb[j] + ex - 127);
        mbt[j] = bits & 0x007fffff;
    }
    int Pm1 = max(Et[0], Et[1]);
    int Pm2 = max(Pm1, Et[2]);
    int Pm3 = max(Pm2, Et[3]);
    int M   = max(Pm3, Et[4]);
    int Sm4 = Et[4];
    int Sm3 = max(Et[3], Sm4);
    int Sm2 = max(Et[2], Sm3);
    int Sm1 = max(Et[1], Sm2);
    int Sm0 = max(Et[0], Sm1);
    int Mp1  = __shfl_down_sync(~0u, M, 1);     if (lane > 30) Mp1  = SENT;
    int Mp2  = __shfl_down_sync(~0u, M, 2);     if (lane > 29) Mp2  = SENT;
    int Mp3  = __shfl_down_sync(~0u, M, 3);     if (lane > 28) Mp3  = SENT;
    int P1p3 = __shfl_down_sync(~0u, Pm1, 3);   if (lane > 28) P1p3 = SENT;
    int P2p3 = __shfl_down_sync(~0u, Pm2, 3);   if (lane > 28) P2p3 = SENT;
    int P3p3 = __shfl_down_sync(~0u, Pm3, 3);   if (lane > 28) P3p3 = SENT;
    int E0p4 = __shfl_down_sync(~0u, Et[0], 4); if (lane > 27) E0p4 = SENT;
    int M12 = max(Mp1, Mp2);
    int E0 = max(max(Sm0, M12), P1p3);
    int E1 = max(max(Sm1, M12), P2p3);
    int E2 = max(max(Sm2, M12), P3p3);
    int E3 = max(max(Sm3, M12), Mp3);
    int E4 = max(max(Sm4, M12), max(Mp3, E0p4));
    int En[NST] = {E0, E1, E2, E3, E4};
#pragma unroll
    for (int j = 0; j < NST; ++j) {
        int d = Et[j] - En[j];
        u[j] = (d < -126 || Et[j] <= SENT) ? 0.0f
             : __int_as_float(mbt[j] | ((d + 127) << 23));
    }
    int E0p1 = __shfl_down_sync(~0u, E0, 1); if (lane > 30) E0p1 = SENT;
    int E1p1 = __shfl_down_sync(~0u, E1, 1); if (lane > 30) E1p1 = SENT;
    int Ep1[NST] = {E1, E2, E3, E4, E0p1};
    int Ep2[NST] = {E2, E3, E4, E0p1, E1p1};
    float sb[NST], sc[NST];
#pragma unroll
    for (int j = 0; j < NST; ++j) {
        int db = min(Ep1[j] - En[j], 126);
        sb[j] = (db < -126 || Ep1[j] <= SENT) ? 0.0f : mkscale(db);
        int dc = min(Ep2[j] - En[j], 126);
        float scv = (dc < -126 || Ep2[j] <= SENT) ? 0.0f : mkscale(dc);
        sc[j] = sk2m[j] ? scv : 0.0f;
        Eb[j] = En[j];
    }
#pragma unroll
    for (int k = 0; k < RSTEPS; ++k) {
        if (FULL || (t0 - k >= tmp1)) {
            float d0 = __shfl_down_sync(~0u, u[0], 1);
            float d1 = __shfl_down_sync(~0u, u[1], 1);
            if (lane == 31) { d0 = 0.0f; d1 = 0.0f; }
            float n0 = fmaf(u[2], sc[0], fmaf(u[1], sb[0], u[0])) * P[k][0];
            float n1 = fmaf(u[3], sc[1], fmaf(u[2], sb[1], u[1])) * P[k][1];
            float n2 = fmaf(u[4], sc[2], fmaf(u[3], sb[2], u[2])) * P[k][2];
            float n3 = fmaf(d0,   sc[3], fmaf(u[4], sb[3], u[3])) * P[k][3];
            float n4 = fmaf(d1,   sc[4], fmaf(d0,   sb[4], u[4])) * P[k][4];
            u[0] = n0; u[1] = n1; u[2] = n2; u[3] = n3; u[4] = n4;
        }
    }
}

__device__ __forceinline__ void loader_warp(
    const float* src, size_t BC,
    int t_begin, int cnt, int stride, int lo, int hi,
    float (*ring)[NST * 32], int* progP,
    volatile int* consP, int consSign,
    float* scratch, const int* lab2, int lane)
{
    float4 Aa[DEPTH], Ab[DEPTH];
    int tq = t_begin;
#pragma unroll
    for (int k = 0; k < DEPTH; ++k) {
        int tt = iclamp(tq, lo, hi);
        const float* r = src + (size_t)tt * BC;
        Aa[k] = *(const float4*)r;
        Ab[k] = *(const float4*)(r + 4);
        tq += stride;
    }
    int t = t_begin;
    int consv = *consP;
    const int c0 = lane * 8;
    while (cnt > 0) {
#pragma unroll
        for (int k = 0; k < DEPTH; ++k) {
            if (cnt > 0) {
                for (;;) {
                    int lead = (consSign > 0) ? (t - consv) : (consv - t);
                    if (lead < LEAD) break;
                    __nanosleep(20);
                    consv = *consP;
                }
                float* scr = scratch + c0;
                ((float4*)scr)[0] = Aa[k];
                ((float4*)scr)[1] = Ab[k];
                __syncwarp();
                float* dst = ring[t & (RD - 1)];
#pragma unroll
                for (int j = 0; j < NST; ++j)
                    dst[j * 32 + lane] = __expf(scratch[lab2[j]]);
                __syncwarp();
                if (lane == 0) st_release_cta(progP, t);
                int tt = iclamp(tq, lo, hi);
                const float* r = src + (size_t)tt * BC;
                Aa[k] = *(const float4*)r;
                Ab[k] = *(const float4*)(r + 4);
                tq += stride;
                t += stride;
                --cnt;
            }
        }
    }
    __syncwarp();
    if (lane == 0)
        st_release_cta(progP, (consSign > 0) ? 0x3fffffff : -0x3fffffff);
}

__global__ void __launch_bounds__(256, 2)
ctc_split2_kernel(const float* __restrict__ logp,
                  const int*   __restrict__ targets,
                  const int*   __restrict__ in_len,
                  const int*   __restrict__ tgt_len,
                  float*       __restrict__ out,
                  int T, int B, int C, int S)
{
    const int b    = blockIdx.x >> 1;
    const int dir  = blockIdx.x & 1;
    const int tid  = threadIdx.x;
    const int w    = tid >> 5;
    const int lane = tid & 31;
    const int L    = 2 * S + 1;
    const int* tgt = targets + (size_t)b * S;

    __shared__ __align__(16) float ring[RD][NST * 32];
    __shared__ __align__(16) float scratchA[NLD][256];
    __shared__ int          prog[NLD];
    __shared__ volatile int cons;
    __shared__ float        red[8];
    __shared__ int          s_flags;

    const size_t BC   = (size_t)B * C;
    const float* base = logp + (size_t)b * C;

    int len = in_len[b];
    if (len > T) len = T;
    if (len < 1) len = 1;
    const int lenm1 = len - 1;
    const int tm    = lenm1 >> 1;
    const int tmp1  = tm + 1;
    const bool use_gamma = (lenm1 > tm);

    if (tid == 0) { cons = dir ? len : 0; s_flags = 0; }
    if (tid < NLD) prog[tid] = dir ? (len + 8) : 0;
    __syncthreads();

    float* outv = &g_fv[dir][b][0];
    int*   oute = &g_fe[dir][b][0];

    if (w == 0 && dir == 0) {
        // ================= forward compute (alpha) =================
        int skm[NST];
#pragma unroll
        for (int j = 0; j < NST; ++j) {
            int s = lane * NST + j;
            int sk = 0;
            if (s < L && s >= 3 && (s & 1)) {
                int lab = tgt[s >> 1];
                int lm2 = tgt[(s - 2) >> 1];
                if (lab != 0 && lab != lm2) sk = 1;
            }
            skm[j] = sk;
        }
        float u[NST]; int Eb[NST];
#pragma unroll
        for (int j = 0; j < NST; ++j) { u[j] = 0.0f; Eb[j] = SENT; }
        if (lane == 0) {
            float y0 = __ldg(base) * 1.4426950408889634f;
            float f0 = floorf(y0); Eb[0] = (int)f0; u[0] = exp2f(y0 - f0);
            if (L > 1) {
                int lab1 = tgt[0];
                float y1 = __ldg(base + lab1) * 1.4426950408889634f;
                float f1 = floorf(y1); Eb[1] = (int)f1; u[1] = exp2f(y1 - f1);
            }
        }

        int mn = 0;
        const int nfull = tm >> 3;
        for (int i = 0; i < nfull; ++i) {
            const int t0   = 1 + (i << 3);
            const int tend = t0 + RSTEPS - 1;
            if (mn < tend) {
                do {
                    mn = ld_acquire_cta(&prog[0]);
#pragma unroll
                    for (int q = 1; q < NLD; ++q)
                        mn = min(mn, ld_acquire_cta(&prog[q]));
                } while (mn < tend);
            }
            fwd_block<true>(t0, tm, lane, ring, skm, u, Eb);
            if (lane == 0) cons = tend;
        }
        {
            const int t0 = 1 + (nfull << 3);
            if (t0 <= tm) {
                if (mn < tm) {
                    do {
                        mn = ld_acquire_cta(&prog[0]);
#pragma unroll
                        for (int q = 1; q < NLD; ++q)
                            mn = min(mn, ld_acquire_cta(&prog[q]));
                    } while (mn < tm);
                }
                fwd_block<false>(t0, tm, lane, ring, skm, u, Eb);
                if (lane == 0) cons = tm;
            }
        }
#pragma unroll
        for (int j = 0; j < NST; ++j) {
            int bits = __float_as_int(u[j]);
            int ex   = (bits >> 23) & 0xff;
            oute[lane * NST + j] = (ex == 0) ? SENT : (Eb[j] + ex - 127);
            outv[lane * NST + j] = (ex == 0) ? 0.0f
                                 : __int_as_float((bits & 0x007fffff) | 0x3f800000);
        }
    } else if (w == 0) {
        // ================= backward compute (gamma) =================
        int sk2m[NST];
#pragma unroll
        for (int j = 0; j < NST; ++j) {
            int s = lane * NST + j;
            int sk = 0;
            if ((s & 1) && (s + 2 <= L - 1)) {
                int lab  = tgt[s >> 1];
                int labp = tgt[(s >> 1) + 1];
                if (labp != 0 && labp != lab) sk = 1;
            }
            sk2m[j] = sk;
        }
        float u[NST]; int Eb[NST];
#pragma unroll
        for (int j = 0; j < NST; ++j) { u[j] = 0.0f; Eb[j] = SENT; }

        if (use_gamma) {
            int tl = tgt_len[b];
            int hi = 2 * tl; if (hi > L - 1) hi = L - 1;
            {
                int mx;
                do {
                    mx = ld_acquire_cta(&prog[0]);
#pragma unroll
                    for (int q = 1; q < NLD; ++q)
                        mx = max(mx, ld_acquire_cta(&prog[q]));
                } while (mx > lenm1);
                const float* rp = &ring[lenm1 & (RD - 1)][0];
#pragma unroll
                for (int j = 0; j < NST; ++j) {
                    int s = lane * NST + j;
                    if (tl > 0 && (s == hi || s == hi - 1)) {
                        u[j]  = rp[j * 32 + lane];
                        Eb[j] = 0;
                    }
                }
                if (lane == 0) cons = lenm1;
            }
            int mx = lenm1;
            const int cntB   = lenm1 - tmp1;     // steps after init
            const int nfullB = cntB >> 3;
            for (int i = 0; i < nfullB; ++i) {
                const int t0   = lenm1 - 1 - (i << 3);
                const int tlow = t0 - RSTEPS + 1;
                if (mx > tlow) {
                    do {
                        mx = ld_acquire_cta(&prog[0]);
#pragma unroll
                        for (int q = 1; q < NLD; ++q)
                            mx = max(mx, ld_acquire_cta(&prog[q]));
                    } while (mx > tlow);
                }
                bwd_block<true>(t0, tmp1, lane, ring, sk2m, u, Eb);
                if (lane == 0) cons = tlow;
            }
            {
                const int t0 = lenm1 - 1 - (nfullB << 3);
                if (t0 >= tmp1) {
                    if (mx > tmp1) {
                        do {
                            mx = ld_acquire_cta(&prog[0]);
#pragma unroll
                            for (int q = 1; q < NLD; ++q)
                                mx = max(mx, ld_acquire_cta(&prog[q]));
                        } while (mx > tmp1);
                    }
                    bwd_block<false>(t0, tmp1, lane, ring, sk2m, u, Eb);
                    if (lane == 0) cons = tmp1;
                }
            }
        }
#pragma unroll
        for (int j = 0; j < NST; ++j) {
            int bits = __float_as_int(u[j]);
            int ex   = (bits >> 23) & 0xff;
            oute[lane * NST + j] = (ex == 0) ? SENT : (Eb[j] + ex - 127);
            outv[lane * NST + j] = (ex == 0) ? 0.0f
                                 : __int_as_float((bits & 0x007fffff) | 0x3f800000);
        }
    } else {
        // ================= loader warps (1..7) =================
        int lab2[NST];
#pragma unroll
        for (int j = 0; j < NST; ++j) {
            int s = lane * NST + j;
            int lab = 0;
            if (s < L && (s & 1)) lab = tgt[s >> 1];
            lab2[j] = lab;
        }
        const float* src = base + lane * 8;
        int i = w - 1;
        if (dir == 0) {
            int cnt = (tm >= 1 + i) ? ((tm - 1 - i) / NLD + 1) : 0;
            loader_warp(src, BC, 1 + i, cnt, NLD, 1, max(tm, 1),
                        ring, &prog[i], &cons, +1, &scratchA[i][0], lab2, lane);
        } else {
            int start = lenm1 - i;
            int cnt = (start >= tmp1) ? ((start - tmp1) / NLD + 1) : 0;
            int lo = min(tmp1, lenm1); if (lo < 0) lo = 0;
            loader_warp(src, BC, start, cnt, -NLD, lo, lenm1,
                        ring, &prog[i], &cons, -1, &scratchA[i][0], lab2, lane);
        }
    }
    __syncthreads();

    // ---- pair rendezvous: second CTA combines ----
    if (tid == 0) {
        __threadfence();
        int old = atomicAdd(&g_pair[b], 1);
        if (old == 1) s_flags = 1;
    }
    __syncthreads();

    if ((s_flags & 1) && w == 0) {
        __threadfence();
        const float* avF = &g_fv[0][b][0]; const int* aeF = &g_fe[0][b][0];
        const float* gvB = &g_fv[1][b][0]; const int* geB = &g_fe[1][b][0];
        int tl = tgt_len[b];
        int hi = 2 * tl; if (hi > L - 1) hi = L - 1;
        float Tv[NST]; int Te[NST];
#pragma unroll
        for (int j = 0; j < NST; ++j) { Tv[j] = 0.0f; Te[j] = SENT; }
        if (tl > 0) {
#pragma unroll
            for (int j = 0; j < NST; ++j) {
                int s = lane * NST + j;
                if (s < L) {
                    float va = avF[s]; int ea = aeF[s];
                    if (va != 0.0f) {
                        if (use_gamma) {
                            float g0v = gvB[s];     int g0e = geB[s];
                            float g1v = 0.0f;       int g1e = SENT;
                            float g2v = 0.0f;       int g2e = SENT;
                            if (s + 1 <= L - 1) { g1v = gvB[s + 1]; g1e = geB[s + 1]; }
                            int sk2 = 0;
                            if ((s & 1) && (s + 2 <= L - 1)) {
                                int lab  = tgt[s >> 1];
                                int labp = tgt[(s >> 1) + 1];
                                if (labp != 0 && labp != lab) sk2 = 1;
                            }
                            if (sk2) { g2v = gvB[s + 2]; g2e = geB[s + 2]; }
                            if (g0v == 0.0f) g0e = SENT;
                            if (g1v == 0.0f) g1e = SENT;
                            if (g2v == 0.0f) g2e = SENT;
                            int m = max(g0e, max(g1e, g2e));
                            if (m > SENT / 2) {
                                float bsum = 0.0f;
                                if (g0e > SENT / 2 && g0e - m >= -126) bsum += g0v * mkscale(g0e - m);
                                if (g1e > SENT / 2 && g1e - m >= -126) bsum += g1v * mkscale(g1e - m);
                                if (g2e > SENT / 2 && g2e - m >= -126) bsum += g2v * mkscale(g2e - m);
                                if (bsum > 0.0f) { Tv[j] = va * bsum; Te[j] = ea + m; }
                            }
                        } else {
                            if (s == hi || s == hi - 1) { Tv[j] = va; Te[j] = ea; }
                        }
                    }
                }
            }
        }
        int M = SENT;
#pragma unroll
        for (int j = 0; j < NST; ++j) if (Tv[j] > 0.0f) M = max(M, Te[j]);
#pragma unroll
        for (int o = 16; o > 0; o >>= 1)
            M = max(M, __shfl_xor_sync(~0u, M, o));
        double acc = 0.0;
#pragma unroll
        for (int j = 0; j < NST; ++j) {
            if (Tv[j] > 0.0f) {
                long long d = (long long)Te[j] - M;
                if (d > -1000) {
                    unsigned long long bits2 = (unsigned long long)(d + 1023) << 52;
                    acc += (double)Tv[j] * __longlong_as_double((long long)bits2);
                }
            }
        }
#pragma unroll
        for (int o = 16; o > 0; o >>= 1)
            acc += __shfl_xor_sync(~0u, acc, o);
        if (lane == 0) {
            float loss = 0.0f;
            if (tl > 0 && acc > 0.0 && M > SENT / 2) {
                double ll = ((double)M + log2(acc)) * 0.69314718055994530942;
                loss = (float)(-ll / (double)tl);
            }
            g_loss[b] = loss;
            g_pair[b] = 0;
            __threadfence();
            unsigned old = atomicAdd(&g_cnt, 1);
            if (old == (unsigned)(B - 1)) s_flags |= 2;
        }
    }
    __syncthreads();

    if (s_flags & 2) {
        __threadfence();
        float acc2 = 0.0f;
        for (int i2 = tid; i2 < B; i2 += 256) acc2 += g_loss[i2];
#pragma unroll
        for (int o = 16; o > 0; o >>= 1)
            acc2 += __shfl_xor_sync(~0u, acc2, o);
        if (lane == 0) red[w] = acc2;
        __syncthreads();
        if (tid == 0) {
            float s8 = 0.0f;
#pragma unroll
            for (int k = 0; k < 8; ++k) s8 += red[k];
            out[0] = s8 / (float)B;
            g_cnt = 0;
        }
    }
}

extern "C" void kernel_launch(void* const* d_in, const int* in_sizes, int n_in,
                              void* d_out, int out_size)
{
    const float* logp    = (const float*)d_in[0];
    const int*   targets = (const int*)d_in[1];
    const int*   in_len  = (const int*)d_in[2];
    const int*   tgt_len = (const int*)d_in[3];

    int B = in_sizes[2];                                   // 128
    int S = in_sizes[1] / B;                               // 64
    int C = 256;
    int T = (int)((size_t)in_sizes[0] / ((size_t)B * C));  // 1024

    ctc_split2_kernel<<<2 * B, 256>>>(logp, targets, in_len, tgt_len,
                                      (float*)d_out, T, B, C, S);
}

// round 16
// speedup vs baseline: 2.1583x; 1.1063x over previous
#include <cuda_runtime.h>

// CTC loss. Two CTAs per batch element: dir 0 = forward alpha over t=1..tm,
// dir 1 = backward gamma over t=len-1..tm+1. Each CTA: 1 compute warp +
// 7 loader warps. Extended-range u*2^E arithmetic, block-rebase every 8 steps.
// Unguarded full blocks + guarded tail (R15). R16: RD=64 / LEAD=56 ring in
// dynamic shared memory -> 7 blocks of producer slack, cadence decoupled.

#define NST    5
#define RSTEPS 8
#define RD     64
#define LEAD   56
#define DEPTH  6
#define NLD    7
#define SENT   (-(1 << 28))

#define RING_B  (RD * NST * 32 * 4)          // 40960
#define SCR_B   (NLD * 256 * 4)              // 7168
#define SMEM_TOT (RING_B + SCR_B + 4 * (NLD + 1 + 8 + 1) + 32)

__device__ float    g_loss[1024];
__device__ unsigned g_cnt = 0;
__device__ int      g_pair[1024];
__device__ float    g_fv[2][1024][NST * 32];
__device__ int      g_fe[2][1024][NST * 32];

__device__ __forceinline__ void st_release_cta(int* p, int v) {
    asm volatile("st.release.cta.b32 [%0], %1;" :: "l"(p), "r"(v) : "memory");
}
__device__ __forceinline__ int ld_acquire_cta(const int* p) {
    int v;
    asm volatile("ld.acquire.cta.b32 %0, [%1];" : "=r"(v) : "l"(p) : "memory");
    return v;
}
__device__ __forceinline__ int iclamp(int x, int lo, int hi) {
    return min(max(x, lo), hi);
}
__device__ __forceinline__ float mkscale(int d) {
    return __int_as_float((d + 127) << 23);
}

// ---------------- forward block (8 steps) ----------------
template<bool FULL>
__device__ __forceinline__ void fwd_block(
    int t0, int tm, int lane,
    float (*ring)[NST * 32],
    const int (&skm)[NST], float (&u)[NST], int (&Eb)[NST])
{
    float P[RSTEPS][NST];
#pragma unroll
    for (int k = 0; k < RSTEPS; ++k) {
        int t = t0 + k;
        if (!FULL) { if (t > tm) t = tm; }
        const float* rp = &ring[t & (RD - 1)][0];
#pragma unroll
        for (int j = 0; j < NST; ++j) P[k][j] = rp[j * 32 + lane];
    }
    int Et[NST], mbt[NST];
#pragma unroll
    for (int j = 0; j < NST; ++j) {
        int bits = __float_as_int(u[j]);
        int ex   = (bits >> 23) & 0xff;
        Et[j]  = (ex == 0) ? SENT : (Eb[j] + ex - 127);
        mbt[j] = bits & 0x007fffff;
    }
    int P0 = Et[0];
    int P1 = max(P0, Et[1]);
    int P2 = max(P1, Et[2]);
    int P3 = max(P2, Et[3]);
    int P4 = max(P3, Et[4]);
    int S4 = Et[4];
    int S3 = max(Et[3], S4);
    int S2 = max(Et[2], S3);
    int S1 = max(Et[1], S2);
    int Mm1  = __shfl_up_sync(~0u, P4, 1);    if (lane < 1) Mm1  = SENT;
    int Mm2  = __shfl_up_sync(~0u, P4, 2);    if (lane < 2) Mm2  = SENT;
    int Mm3  = __shfl_up_sync(~0u, P4, 3);    if (lane < 3) Mm3  = SENT;
    int S1m3 = __shfl_up_sync(~0u, S1, 3);    if (lane < 3) S1m3 = SENT;
    int S2m3 = __shfl_up_sync(~0u, S2, 3);    if (lane < 3) S2m3 = SENT;
    int S3m3 = __shfl_up_sync(~0u, S3, 3);    if (lane < 3) S3m3 = SENT;
    int E4m4 = __shfl_up_sync(~0u, Et[4], 4); if (lane < 4) E4m4 = SENT;
    int M12 = max(Mm1, Mm2);
    int E0 = max(max(P0, M12), max(Mm3, E4m4));
    int E1 = max(max(P1, M12), Mm3);
    int E2 = max(max(P2, M12), S1m3);
    int E3 = max(max(P3, M12), S2m3);
    int E4 = max(max(P4, M12), S3m3);
    int En[NST] = {E0, E1, E2, E3, E4};
#pragma unroll
    for (int j = 0; j < NST; ++j) {
        int d = Et[j] - En[j];
        u[j] = (d < -126 || Et[j] <= SENT) ? 0.0f
             : __int_as_float(mbt[j] | ((d + 127) << 23));
    }
    int E4m1 = __shfl_up_sync(~0u, E4, 1); if (lane < 1) E4m1 = SENT;
    int E3m1 = __shfl_up_sync(~0u, E3, 1); if (lane < 1) E3m1 = SENT;
    int Em1[NST] = {E4m1, E0, E1, E2, E3};
    int Em2[NST] = {E3m1, E4m1, E0, E1, E2};
    float sb[NST], sc[NST];
#pragma unroll
    for (int j = 0; j < NST; ++j) {
        int db = min(Em1[j] - En[j], 126);
        sb[j] = (db < -126 || Em1[j] <= SENT) ? 0.0f : mkscale(db);
        int dc = min(Em2[j] - En[j], 126);
        float scv = (dc < -126 || Em2[j] <= SENT) ? 0.0f : mkscale(dc);
        sc[j] = skm[j] ? scv : 0.0f;
        Eb[j] = En[j];
    }
#pragma unroll
    for (int k = 0; k < RSTEPS; ++k) {
        if (FULL || (t0 + k <= tm)) {
            float vm1 = __shfl_up_sync(~0u, u[4], 1);
            float vm2 = __shfl_up_sync(~0u, u[3], 1);
            if (lane == 0) { vm1 = 0.0f; vm2 = 0.0f; }
            float n0 = fmaf(vm2,  sc[0], fmaf(vm1,  sb[0], u[0])) * P[k][0];
            float n1 = fmaf(vm1,  sc[1], fmaf(u[0], sb[1], u[1])) * P[k][1];
            float n2 = fmaf(u[0], sc[2], fmaf(u[1], sb[2], u[2])) * P[k][2];
            float n3 = fmaf(u[1], sc[3], fmaf(u[2], sb[3], u[3])) * P[k][3];
            float n4 = fmaf(u[2], sc[4], fmaf(u[3], sb[4], u[4])) * P[k][4];
            u[0] = n0; u[1] = n1; u[2] = n2; u[3] = n3; u[4] = n4;
        }
    }
}

// ---------------- backward block (8 steps, descending t) ----------------
template<bool FULL>
__device__ __forceinline__ void bwd_block(
    int t0, int tmp1, int lane,
    float (*ring)[NST * 32],
    const int (&sk2m)[NST], float (&u)[NST], int (&Eb)[NST])
{
    float P[RSTEPS][NST];
#pragma unroll
    for (int k = 0; k < RSTEPS; ++k) {
        int t = t0 - k;
        if (!FULL) { if (t < tmp1) t = tmp1; }
        const float* rp = &ring[t & (RD - 1)][0];
#pragma unroll
        for (int j = 0; j < NST; ++j) P[k][j] = rp[j * 32 + lane];
    }
    int Et[NST], mbt[NST];
#pragma unroll
    for (int j = 0; j < NST; ++j) {
        int bits = __float_as_int(u[j]);
        int ex   = (bits >> 23) & 0xff;
        Et[j]  = (ex == 0) ? SENT : (Eb[j] + ex - 127);
        mbt[j] = bits & 0x007fffff;
    }
    int Pm1 = max(Et[0], Et[1]);
    int Pm2 = max(Pm1, Et[2]);
    int Pm3 = max(Pm2, Et[3]);
    int M   = max(Pm3, Et[4]);
    int Sm4 = Et[4];
    int Sm3 = max(Et[3], Sm4);
    int Sm2 = max(Et[2], Sm3);
    int Sm1 = max(Et[1], Sm2);
    int Sm0 = max(Et[0], Sm1);
    int Mp1  = __shfl_down_sync(~0u, M, 1);     if (lane > 30) Mp1  = SENT;
    int Mp2  = __shfl_down_sync(~0u, M, 2);     if (lane > 29) Mp2  = SENT;
    int Mp3  = __shfl_down_sync(~0u, M, 3);     if (lane > 28) Mp3  = SENT;
    int P1p3 = __shfl_down_sync(~0u, Pm1, 3);   if (lane > 28) P1p3 = SENT;
    int P2p3 = __shfl_down_sync(~0u, Pm2, 3);   if (lane > 28) P2p3 = SENT;
    int P3p3 = __shfl_down_sync(~0u, Pm3, 3);   if (lane > 28) P3p3 = SENT;
    int E0p4 = __shfl_down_sync(~0u, Et[0], 4); if (lane > 27) E0p4 = SENT;
    int M12 = max(Mp1, Mp2);
    int E0 = max(max(Sm0, M12), P1p3);
    int E1 = max(max(Sm1, M12), P2p3);
    int E2 = max(max(Sm2, M12), P3p3);
    int E3 = max(max(Sm3, M12), Mp3);
    int E4 = max(max(Sm4, M12), max(Mp3, E0p4));
    int En[NST] = {E0, E1, E2, E3, E4};
#pragma unroll
    for (int j = 0; j < NST; ++j) {
        int d = Et[j] - En[j];
        u[j] = (d < -126 || Et[j] <= SENT) ? 0.0f
             : __int_as_float(mbt[j] | ((d + 127) << 23));
    }
    int E0p1 = __shfl_down_sync(~0u, E0, 1); if (lane > 30) E0p1 = SENT;
    int E1p1 = __shfl_down_sync(~0u, E1, 1); if (lane > 30) E1p1 = SENT;
    int Ep1[NST] = {E1, E2, E3, E4, E0p1};
    int Ep2[NST] = {E2, E3, E4, E0p1, E1p1};
    float sb[NST], sc[NST];
#pragma unroll
    for (int j = 0; j < NST; ++j) {
        int db = min(Ep1[j] - En[j], 126);
        sb[j] = (db < -126 || Ep1[j] <= SENT) ? 0.0f : mkscale(db);
        int dc = min(Ep2[j] - En[j], 126);
        float scv = (dc < -126 || Ep2[j] <= SENT) ? 0.0f : mkscale(dc);
        sc[j] = sk2m[j] ? scv : 0.0f;
        Eb[j] = En[j];
    }
#pragma unroll
    for (int k = 0; k < RSTEPS; ++k) {
        if (FULL || (t0 - k >= tmp1)) {
            float d0 = __shfl_down_sync(~0u, u[0], 1);
            float d1 = __shfl_down_sync(~0u, u[1], 1);
            if (lane == 31) { d0 = 0.0f; d1 = 0.0f; }
            float n0 = fmaf(u[2], sc[0], fmaf(u[1], sb[0], u[0])) * P[k][0];
            float n1 = fmaf(u[3], sc[1], fmaf(u[2], sb[1], u[1])) * P[k][1];
            float n2 = fmaf(u[4], sc[2], fmaf(u[3], sb[2], u[2])) * P[k][2];
            float n3 = fmaf(d0,   sc[3], fmaf(u[4], sb[3], u[3])) * P[k][3];
            float n4 = fmaf(d1,   sc[4], fmaf(d0,   sb[4], u[4])) * P[k][4];
            u[0] = n0; u[1] = n1; u[2] = n2; u[3] = n3; u[4] = n4;
        }
    }
}

__device__ __forceinline__ void loader_warp(
    const float* src, size_t BC,
    int t_begin, int cnt, int stride, int lo, int hi,
    float (*ring)[NST * 32], int* progP,
    volatile int* consP, int consSign,
    float* scratch, const int* lab2, int lane)
{
    float4 Aa[DEPTH], Ab[DEPTH];
    int tq = t_begin;
#pragma unroll
    for (int k = 0; k < DEPTH; ++k) {
        int tt = iclamp(tq, lo, hi);
        const float* r = src + (size_t)tt * BC;
        Aa[k] = *(const float4*)r;
        Ab[k] = *(const float4*)(r + 4);
        tq += stride;
    }
    int t = t_begin;
    int consv = *consP;
    const int c0 = lane * 8;
    while (cnt > 0) {
#pragma unroll
        for (int k = 0; k < DEPTH; ++k) {
            if (cnt > 0) {
                for (;;) {
                    int lead = (consSign > 0) ? (t - consv) : (consv - t);
                    if (lead < LEAD) break;
                    __nanosleep(20);
                    consv = *consP;
                }
                float* scr = scratch + c0;
                ((float4*)scr)[0] = Aa[k];
                ((float4*)scr)[1] = Ab[k];
                __syncwarp();
                float* dst = ring[t & (RD - 1)];
#pragma unroll
                for (int j = 0; j < NST; ++j)
                    dst[j * 32 + lane] = __expf(scratch[lab2[j]]);
                __syncwarp();
                if (lane == 0) st_release_cta(progP, t);
                int tt = iclamp(tq, lo, hi);
                const float* r = src + (size_t)tt * BC;
                Aa[k] = *(const float4*)r;
                Ab[k] = *(const float4*)(r + 4);
                tq += stride;
                t += stride;
                --cnt;
            }
        }
    }
    __syncwarp();
    if (lane == 0)
        st_release_cta(progP, (consSign > 0) ? 0x3fffffff : -0x3fffffff);
}

__global__ void __launch_bounds__(256, 2)
ctc_split3_kernel(const float* __restrict__ logp,
                  const int*   __restrict__ targets,
                  const int*   __restrict__ in_len,
                  const int*   __restrict__ tgt_len,
                  float*       __restrict__ out,
                  int T, int B, int C, int S)
{
    const int b    = blockIdx.x >> 1;
    const int dir  = blockIdx.x & 1;
    const int tid  = threadIdx.x;
    const int w    = tid >> 5;
    const int lane = tid & 31;
    const int L    = 2 * S + 1;
    const int* tgt = targets + (size_t)b * S;

    extern __shared__ __align__(16) char dsm[];
    float (*ring)[NST * 32]    = (float(*)[NST * 32])dsm;
    float (*scratchA)[256]     = (float(*)[256])(dsm + RING_B);
    int*  prog                 = (int*)(dsm + RING_B + SCR_B);
    volatile int* consP        = (volatile int*)(prog + NLD);
    float* red                 = (float*)(prog + NLD + 1);
    int*   s_flagsP            = (int*)(red + 8);

    const size_t BC   = (size_t)B * C;
    const float* base = logp + (size_t)b * C;

    int len = in_len[b];
    if (len > T) len = T;
    if (len < 1) len = 1;
    const int lenm1 = len - 1;
    const int tm    = lenm1 >> 1;
    const int tmp1  = tm + 1;
    const bool use_gamma = (lenm1 > tm);

    if (tid == 0) { *consP = dir ? len : 0; *s_flagsP = 0; }
    if (tid < NLD) prog[tid] = dir ? (len + 8) : 0;
    __syncthreads();

    float* outv = &g_fv[dir][b][0];
    int*   oute = &g_fe[dir][b][0];

    if (w == 0 && dir == 0) {
        // ================= forward compute (alpha) =================
        int skm[NST];
#pragma unroll
        for (int j = 0; j < NST; ++j) {
            int s = lane * NST + j;
            int sk = 0;
            if (s < L && s >= 3 && (s & 1)) {
                int lab = tgt[s >> 1];
                int lm2 = tgt[(s - 2) >> 1];
                if (lab != 0 && lab != lm2) sk = 1;
            }
            skm[j] = sk;
        }
        float u[NST]; int Eb[NST];
#pragma unroll
        for (int j = 0; j < NST; ++j) { u[j] = 0.0f; Eb[j] = SENT; }
        if (lane == 0) {
            float y0 = __ldg(base) * 1.4426950408889634f;
            float f0 = floorf(y0); Eb[0] = (int)f0; u[0] = exp2f(y0 - f0);
            if (L > 1) {
                int lab1 = tgt[0];
                float y1 = __ldg(base + lab1) * 1.4426950408889634f;
                float f1 = floorf(y1); Eb[1] = (int)f1; u[1] = exp2f(y1 - f1);
            }
        }

        int mn = 0;
        const int nfull = tm >> 3;
        for (int i = 0; i < nfull; ++i) {
            const int t0   = 1 + (i << 3);
            const int tend = t0 + RSTEPS - 1;
            if (mn < tend) {
                do {
                    mn = ld_acquire_cta(&prog[0]);
#pragma unroll
                    for (int q = 1; q < NLD; ++q)
                        mn = min(mn, ld_acquire_cta(&prog[q]));
                } while (mn < tend);
            }
            fwd_block<true>(t0, tm, lane, ring, skm, u, Eb);
            if (lane == 0) *consP = tend;
        }
        {
            const int t0 = 1 + (nfull << 3);
            if (t0 <= tm) {
                if (mn < tm) {
                    do {
                        mn = ld_acquire_cta(&prog[0]);
#pragma unroll
                        for (int q = 1; q < NLD; ++q)
                            mn = min(mn, ld_acquire_cta(&prog[q]));
                    } while (mn < tm);
                }
                fwd_block<false>(t0, tm, lane, ring, skm, u, Eb);
                if (lane == 0) *consP = tm;
            }
        }
#pragma unroll
        for (int j = 0; j < NST; ++j) {
            int bits = __float_as_int(u[j]);
            int ex   = (bits >> 23) & 0xff;
            oute[lane * NST + j] = (ex == 0) ? SENT : (Eb[j] + ex - 127);
            outv[lane * NST + j] = (ex == 0) ? 0.0f
                                 : __int_as_float((bits & 0x007fffff) | 0x3f800000);
        }
    } else if (w == 0) {
        // ================= backward compute (gamma) =================
        int sk2m[NST];
#pragma unroll
        for (int j = 0; j < NST; ++j) {
            int s = lane * NST + j;
            int sk = 0;
            if ((s & 1) && (s + 2 <= L - 1)) {
                int lab  = tgt[s >> 1];
                int labp = tgt[(s >> 1) + 1];
                if (labp != 0 && labp != lab) sk = 1;
            }
            sk2m[j] = sk;
        }
        float u[NST]; int Eb[NST];
#pragma unroll
        for (int j = 0; j < NST; ++j) { u[j] = 0.0f; Eb[j] = SENT; }

        if (use_gamma) {
            int tl = tgt_len[b];
            int hi = 2 * tl; if (hi > L - 1) hi = L - 1;
            {
                int mx;
                do {
                    mx = ld_acquire_cta(&prog[0]);
#pragma unroll
                    for (int q = 1; q < NLD; ++q)
                        mx = max(mx, ld_acquire_cta(&prog[q]));
                } while (mx > lenm1);
                const float* rp = &ring[lenm1 & (RD - 1)][0];
#pragma unroll
                for (int j = 0; j < NST; ++j) {
                    int s = lane * NST + j;
                    if (tl > 0 && (s == hi || s == hi - 1)) {
                        u[j]  = rp[j * 32 + lane];
                        Eb[j] = 0;
                    }
                }
                if (lane == 0) *consP = lenm1;
            }
            int mx = lenm1;
            const int cntB   = lenm1 - tmp1;
            const int nfullB = cntB >> 3;
            for (int i = 0; i < nfullB; ++i) {
                const int t0   = lenm1 - 1 - (i << 3);
                const int tlow = t0 - RSTEPS + 1;
                if (mx > tlow) {
                    do {
                        mx = ld_acquire_cta(&prog[0]);
#pragma unroll
                        for (int q = 1; q < NLD; ++q)
                            mx = max(mx, ld_acquire_cta(&prog[q]));
                    } while (mx > tlow);
                }
                bwd_block<true>(t0, tmp1, lane, ring, sk2m, u, Eb);
                if (lane == 0) *consP = tlow;
            }
            {
                const int t0 = lenm1 - 1 - (nfullB << 3);
                if (t0 >= tmp1) {
                    if (mx > tmp1) {
                        do {
                            mx = ld_acquire_cta(&prog[0]);
#pragma unroll
                            for (int q = 1; q < NLD; ++q)
                                mx = max(mx, ld_acquire_cta(&prog[q]));
                        } while (mx > tmp1);
                    }
                    bwd_block<false>(t0, tmp1, lane, ring, sk2m, u, Eb);
                    if (lane == 0) *consP = tmp1;
                }
            }
        }
#pragma unroll
        for (int j = 0; j < NST; ++j) {
            int bits = __float_as_int(u[j]);
            int ex   = (bits >> 23) & 0xff;
            oute[lane * NST + j] = (ex == 0) ? SENT : (Eb[j] + ex - 127);
            outv[lane * NST + j] = (ex == 0) ? 0.0f
                                 : __int_as_float((bits & 0x007fffff) | 0x3f800000);
        }
    } else {
        // ================= loader warps (1..7) =================
        int lab2[NST];
#pragma unroll
        for (int j = 0; j < NST; ++j) {
            int s = lane * NST + j;
            int lab = 0;
            if (s < L && (s & 1)) lab = tgt[s >> 1];
            lab2[j] = lab;
        }
        const float* src = base + lane * 8;
        int i = w - 1;
        if (dir == 0) {
            int cnt = (tm >= 1 + i) ? ((tm - 1 - i) / NLD + 1) : 0;
            loader_warp(src, BC, 1 + i, cnt, NLD, 1, max(tm, 1),
                        ring, &prog[i], consP, +1, &scratchA[i][0], lab2, lane);
        } else {
            int start = lenm1 - i;
            int cnt = (start >= tmp1) ? ((start - tmp1) / NLD + 1) : 0;
            int lo = min(tmp1, lenm1); if (lo < 0) lo = 0;
            loader_warp(src, BC, start, cnt, -NLD, lo, lenm1,
                        ring, &prog[i], consP, -1, &scratchA[i][0], lab2, lane);
        }
    }
    __syncthreads();

    // ---- pair rendezvous: second CTA combines ----
    if (tid == 0) {
        __threadfence();
        int old = atomicAdd(&g_pair[b], 1);
        if (old == 1) *s_flagsP = 1;
    }
    __syncthreads();

    if ((*s_flagsP & 1) && w == 0) {
        __threadfence();
        const float* avF = &g_fv[0][b][0]; const int* aeF = &g_fe[0][b][0];
        const float* gvB = &g_fv[1][b][0]; const int* geB = &g_fe[1][b][0];
        int tl = tgt_len[b];
        int hi = 2 * tl; if (hi > L - 1) hi = L - 1;
        float Tv[NST]; int Te[NST];
#pragma unroll
        for (int j = 0; j < NST; ++j) { Tv[j] = 0.0f; Te[j] = SENT; }
        if (tl > 0) {
#pragma unroll
            for (int j = 0; j < NST; ++j) {
                int s = lane * NST + j;
                if (s < L) {
                    float va = avF[s]; int ea = aeF[s];
                    if (va != 0.0f) {
                        if (use_gamma) {
                            float g0v = gvB[s];     int g0e = geB[s];
                            float g1v = 0.0f;       int g1e = SENT;
                            float g2v = 0.0f;       int g2e = SENT;
                            if (s + 1 <= L - 1) { g1v = gvB[s + 1]; g1e = geB[s + 1]; }
                            int sk2 = 0;
                            if ((s & 1) && (s + 2 <= L - 1)) {
                                int lab  = tgt[s >> 1];
                                int labp = tgt[(s >> 1) + 1];
                                if (labp != 0 && labp != lab) sk2 = 1;
                            }
                            if (sk2) { g2v = gvB[s + 2]; g2e = geB[s + 2]; }
                            if (g0v == 0.0f) g0e = SENT;
                            if (g1v == 0.0f) g1e = SENT;
                            if (g2v == 0.0f) g2e = SENT;
                            int m = max(g0e, max(g1e, g2e));
                            if (m > SENT / 2) {
                                float bsum = 0.0f;
                                if (g0e > SENT / 2 && g0e - m >= -126) bsum += g0v * mkscale(g0e - m);
                                if (g1e > SENT / 2 && g1e - m >= -126) bsum += g1v * mkscale(g1e - m);
                                if (g2e > SENT / 2 && g2e - m >= -126) bsum += g2v * mkscale(g2e - m);
                                if (bsum > 0.0f) { Tv[j] = va * bsum; Te[j] = ea + m; }
                            }
                        } else {
                            if (s == hi || s == hi - 1) { Tv[j] = va; Te[j] = ea; }
                        }
                    }
                }
            }
        }
        int M = SENT;
#pragma unroll
        for (int j = 0; j < NST; ++j) if (Tv[j] > 0.0f) M = max(M, Te[j]);
#pragma unroll
        for (int o = 16; o > 0; o >>= 1)
            M = max(M, __shfl_xor_sync(~0u, M, o));
        double acc = 0.0;
#pragma unroll
        for (int j = 0; j < NST; ++j) {
            if (Tv[j] > 0.0f) {
                long long d = (long long)Te[j] - M;
                if (d > -1000) {
                    unsigned long long bits2 = (unsigned long long)(d + 1023) << 52;
                    acc += (double)Tv[j] * __longlong_as_double((long long)bits2);
                }
            }
        }
#pragma unroll
        for (int o = 16; o > 0; o >>= 1)
            acc += __shfl_xor_sync(~0u, acc, o);
        if (lane == 0) {
            float loss = 0.0f;
            if (tl > 0 && acc > 0.0 && M > SENT / 2) {
                double ll = ((double)M + log2(acc)) * 0.69314718055994530942;
                loss = (float)(-ll / (double)tl);
            }
            g_loss[b] = loss;
            g_pair[b] = 0;
            __threadfence();
            unsigned old = atomicAdd(&g_cnt, 1);
            if (old == (unsigned)(B - 1)) *s_flagsP |= 2;
        }
    }
    __syncthreads();

    if (*s_flagsP & 2) {
        __threadfence();
        float acc2 = 0.0f;
        for (int i2 = tid; i2 < B; i2 += 256) acc2 += g_loss[i2];
#pragma unroll
        for (int o = 16; o > 0; o >>= 1)
            acc2 += __shfl_xor_sync(~0u, acc2, o);
        if (lane == 0) red[w] = acc2;
        __syncthreads();
        if (tid == 0) {
            float s8 = 0.0f;
#pragma unroll
            for (int k = 0; k < 8; ++k) s8 += red[k];
            out[0] = s8 / (float)B;
            g_cnt = 0;
        }
    }
}

extern "C" void kernel_launch(void* const* d_in, const int* in_sizes, int n_in,
                              void* d_out, int out_size)
{
    const float* logp    = (const float*)d_in[0];
    const int*   targets = (const int*)d_in[1];
    const int*   in_len  = (const int*)d_in[2];
    const int*   tgt_len = (const int*)d_in[3];

    int B = in_sizes[2];                                   // 128
    int S = in_sizes[1] / B;                               // 64
    int C = 256;
    int T = (int)((size_t)in_sizes[0] / ((size_t)B * C));  // 1024

    static int s_attr_done = 0;
    if (!s_attr_done) {
        cudaFuncSetAttribute(ctc_split3_kernel,
                             cudaFuncAttributeMaxDynamicSharedMemorySize, SMEM_TOT);
        s_attr_done = 1;
    }
    ctc_split3_kernel<<<2 * B, 256, SMEM_TOT>>>(logp, targets, in_len, tgt_len,
                                                (float*)d_out, T, B, C, S);
}